// round 1
// baseline (speedup 1.0000x reference)
#include <cuda_runtime.h>
#include <math.h>

#define B_  2
#define T_  2048
#define C_  1024
#define H_  16
#define DH_ 64
#define BT_ (B_*T_)
#define FF_ (4*C_)

// ------------------- device scratch (no allocations allowed) -------------------
__device__ float g_h  [BT_*C_];
__device__ float g_q  [BT_*C_];
__device__ float g_k  [BT_*C_];
__device__ float g_v  [BT_*C_];
__device__ float g_o  [BT_*C_];
__device__ float g_h2 [BT_*C_];
__device__ float g_ff [BT_*FF_];
__device__ float g_sc [(size_t)B_*H_*T_*T_];   // 536 MB scores
__device__ float g_Wqp[C_*C_];
__device__ float g_Wkp[C_*C_];
__device__ float g_Wvp[C_*C_];

// ------------------- block reductions -------------------
__device__ __forceinline__ float block_reduce_sum(float v) {
    __shared__ float sm[8];
    __shared__ float res;
    #pragma unroll
    for (int o = 16; o; o >>= 1) v += __shfl_xor_sync(0xffffffffu, v, o);
    if ((threadIdx.x & 31) == 0) sm[threadIdx.x >> 5] = v;
    __syncthreads();
    if (threadIdx.x < 32) {
        float t = (threadIdx.x < 8) ? sm[threadIdx.x] : 0.f;
        #pragma unroll
        for (int o = 4; o; o >>= 1) t += __shfl_xor_sync(0xffffffffu, t, o);
        if (threadIdx.x == 0) res = t;
    }
    __syncthreads();
    return res;
}

__device__ __forceinline__ float block_reduce_max(float v) {
    __shared__ float sm[8];
    __shared__ float res;
    #pragma unroll
    for (int o = 16; o; o >>= 1) v = fmaxf(v, __shfl_xor_sync(0xffffffffu, v, o));
    if ((threadIdx.x & 31) == 0) sm[threadIdx.x >> 5] = v;
    __syncthreads();
    if (threadIdx.x < 32) {
        float t = (threadIdx.x < 8) ? sm[threadIdx.x] : -3.4e38f;
        #pragma unroll
        for (int o = 4; o; o >>= 1) t = fmaxf(t, __shfl_xor_sync(0xffffffffu, t, o));
        if (threadIdx.x == 0) res = t;
    }
    __syncthreads();
    return res;
}

// ------------------- weight repack: (H, C, Dh) -> (C, H*Dh) -------------------
__global__ void repack_kernel(const float* __restrict__ W, float* __restrict__ out) {
    int idx = blockIdx.x * blockDim.x + threadIdx.x;
    if (idx >= C_ * C_) return;
    int c = idx / C_, n = idx % C_;
    out[idx] = W[((size_t)(n / DH_) * C_ + c) * DH_ + (n % DH_)];
}

// ------------------- layernorm: one block per row of C=1024 -------------------
__global__ void __launch_bounds__(256) ln_kernel(const float* __restrict__ x,
                                                 const float* __restrict__ g,
                                                 const float* __restrict__ b,
                                                 float* __restrict__ out) {
    size_t row = blockIdx.x;
    const float* xr = x + row * C_;
    float v[4]; float s = 0.f;
    #pragma unroll
    for (int i = 0; i < 4; i++) { v[i] = xr[threadIdx.x + i*256]; s += v[i]; }
    float mu = block_reduce_sum(s) * (1.f / C_);
    float s2 = 0.f;
    #pragma unroll
    for (int i = 0; i < 4; i++) { float d = v[i] - mu; s2 += d * d; }
    float rstd = rsqrtf(block_reduce_sum(s2) * (1.f / C_) + 1e-5f);
    float* orow = out + row * C_;
    #pragma unroll
    for (int i = 0; i < 4; i++) {
        int j = threadIdx.x + i*256;
        orow[j] = (v[i] - mu) * rstd * g[j] + b[j];
    }
}

// ------------------- softmax over rows of T=2048 (scale folded in) -------------
__global__ void __launch_bounds__(256) softmax_kernel(float* __restrict__ s) {
    float* r = s + (size_t)blockIdx.x * T_;
    const float scale = 0.03125f;  // C^-0.5 = 1/32
    float v[8]; float mx = -3.4e38f;
    #pragma unroll
    for (int i = 0; i < 8; i++) { v[i] = r[threadIdx.x + i*256] * scale; mx = fmaxf(mx, v[i]); }
    mx = block_reduce_max(mx);
    float sum = 0.f;
    #pragma unroll
    for (int i = 0; i < 8; i++) { v[i] = __expf(v[i] - mx); sum += v[i]; }
    float inv = 1.f / block_reduce_sum(sum);
    #pragma unroll
    for (int i = 0; i < 8; i++) r[threadIdx.x + i*256] = v[i] * inv;
}

// ------------------- generic strided batched SGEMM ------------------------------
// C[m,n] = sum_k A[m,k]*B[k,n] (+bias[n]) (+resid) (relu), arbitrary elem strides,
// batch z = b*Hdim + h with separate (b,h) batch strides.
template<int BM, int BN, int BK, int TM, int TN>
__global__ void __launch_bounds__((BM/TM)*(BN/TN))
gemm_kernel(const float* __restrict__ A, long long rsA, long long csA, long long sAb, long long sAh,
            const float* __restrict__ B, long long rsB, long long csB, long long sBb, long long sBh,
            float* C, long long rsC, long long csC, long long sCb, long long sCh,
            int M, int N, int K, int Hdim,
            const float* __restrict__ bias,
            const float* resid, int relu) {
    constexpr int THREADS = (BM/TM)*(BN/TN);
    __shared__ float As[BK][BM + 4];
    __shared__ float Bs[BK][BN];

    int z = blockIdx.z;
    int bb = z / Hdim, hh = z % Hdim;
    A += bb * sAb + hh * sAh;
    B += bb * sBb + hh * sBh;
    C += bb * sCb + hh * sCh;
    if (resid) resid += bb * sCb + hh * sCh;

    int tid = threadIdx.x;
    int tx = tid % (BN / TN);          // 16
    int ty = tid / (BN / TN);          // 16
    int row0 = blockIdx.y * BM;
    int col0 = blockIdx.x * BN;

    float acc[TM][TN];
    #pragma unroll
    for (int i = 0; i < TM; i++)
        #pragma unroll
        for (int j = 0; j < TN; j++) acc[i][j] = 0.f;

    for (int k0 = 0; k0 < K; k0 += BK) {
        #pragma unroll
        for (int l = tid; l < BM*BK; l += THREADS) {
            int kk = l % BK, m = l / BK;
            As[kk][m] = A[(size_t)(row0 + m) * rsA + (size_t)(k0 + kk) * csA];
        }
        #pragma unroll
        for (int l = tid; l < BK*BN; l += THREADS) {
            int n = l % BN, kk = l / BN;
            Bs[kk][n] = B[(size_t)(k0 + kk) * rsB + (size_t)(col0 + n) * csB];
        }
        __syncthreads();
        #pragma unroll
        for (int kk = 0; kk < BK; kk++) {
            float ra[TM], rb[TN];
            #pragma unroll
            for (int i = 0; i < TM; i++) ra[i] = As[kk][ty*TM + i];
            #pragma unroll
            for (int j = 0; j < TN; j++) rb[j] = Bs[kk][tx*TN + j];
            #pragma unroll
            for (int i = 0; i < TM; i++)
                #pragma unroll
                for (int j = 0; j < TN; j++) acc[i][j] += ra[i] * rb[j];
        }
        __syncthreads();
    }

    #pragma unroll
    for (int i = 0; i < TM; i++) {
        int m = row0 + ty*TM + i;
        #pragma unroll
        for (int j = 0; j < TN; j++) {
            int n = col0 + tx*TN + j;
            float val = acc[i][j];
            if (bias)  val += bias[n];
            size_t ci = (size_t)m * rsC + (size_t)n * csC;
            if (resid) val += resid[ci];
            if (relu)  val = fmaxf(val, 0.f);
            C[ci] = val;
        }
    }
}

// ------------------- launcher ---------------------------------------------------
extern "C" void kernel_launch(void* const* d_in, const int* in_sizes, int n_in,
                              void* d_out, int out_size) {
    const float* x   = (const float*)d_in[0];
    const float* Wq  = (const float*)d_in[1];
    const float* Wk  = (const float*)d_in[2];
    const float* Wv  = (const float*)d_in[3];
    const float* Wo  = (const float*)d_in[4];
    const float* bo  = (const float*)d_in[5];
    const float* W1  = (const float*)d_in[6];
    const float* b1  = (const float*)d_in[7];
    const float* W2  = (const float*)d_in[8];
    const float* b2  = (const float*)d_in[9];
    const float* g1  = (const float*)d_in[10];
    const float* be1 = (const float*)d_in[11];
    const float* g2  = (const float*)d_in[12];
    const float* be2 = (const float*)d_in[13];
    float* out = (float*)d_out;

    float *h, *q, *k, *v, *o, *h2, *ff, *sc, *wqp, *wkp, *wvp;
    cudaGetSymbolAddress((void**)&h,   g_h);
    cudaGetSymbolAddress((void**)&q,   g_q);
    cudaGetSymbolAddress((void**)&k,   g_k);
    cudaGetSymbolAddress((void**)&v,   g_v);
    cudaGetSymbolAddress((void**)&o,   g_o);
    cudaGetSymbolAddress((void**)&h2,  g_h2);
    cudaGetSymbolAddress((void**)&ff,  g_ff);
    cudaGetSymbolAddress((void**)&sc,  g_sc);
    cudaGetSymbolAddress((void**)&wqp, g_Wqp);
    cudaGetSymbolAddress((void**)&wkp, g_Wkp);
    cudaGetSymbolAddress((void**)&wvp, g_Wvp);

    constexpr int BM = 128, BN = 64, BK = 16, TM = 8, TN = 4;
    auto grid = [](int M, int N, int Z) { return dim3(N / BN, M / BM, Z); };

    // repack per-head projection weights to (C, H*Dh)
    repack_kernel<<<(C_*C_ + 255)/256, 256>>>(Wq, wqp);
    repack_kernel<<<(C_*C_ + 255)/256, 256>>>(Wk, wkp);
    repack_kernel<<<(C_*C_ + 255)/256, 256>>>(Wv, wvp);

    // LN1
    ln_kernel<<<BT_, 256>>>(x, g1, be1, h);

    // q/k/v = h @ Wp   (BT x C) @ (C x C), output layout (b,t,h,d)
    gemm_kernel<BM,BN,BK,TM,TN><<<grid(BT_, C_, 1), 256>>>(
        h, C_, 1, 0, 0,  wqp, C_, 1, 0, 0,  q, C_, 1, 0, 0,
        BT_, C_, C_, 1, nullptr, nullptr, 0);
    gemm_kernel<BM,BN,BK,TM,TN><<<grid(BT_, C_, 1), 256>>>(
        h, C_, 1, 0, 0,  wkp, C_, 1, 0, 0,  k, C_, 1, 0, 0,
        BT_, C_, C_, 1, nullptr, nullptr, 0);
    gemm_kernel<BM,BN,BK,TM,TN><<<grid(BT_, C_, 1), 256>>>(
        h, C_, 1, 0, 0,  wvp, C_, 1, 0, 0,  v, C_, 1, 0, 0,
        BT_, C_, C_, 1, nullptr, nullptr, 0);

    // scores[b,h] = q[b,h] (T x Dh) @ k[b,h]^T (Dh x T)
    gemm_kernel<BM,BN,BK,TM,TN><<<grid(T_, T_, B_*H_), 256>>>(
        q,  C_, 1, (long long)T_*C_, DH_,
        k,  1, C_, (long long)T_*C_, DH_,
        sc, T_, 1, (long long)H_*T_*T_, (long long)T_*T_,
        T_, T_, DH_, H_, nullptr, nullptr, 0);

    // softmax (scale 1/32 folded in)
    softmax_kernel<<<B_*H_*T_, 256>>>(sc);

    // o[b,h] = P (T x T) @ v[b,h] (T x Dh), output layout (b,t,h,d)
    gemm_kernel<BM,BN,BK,TM,TN><<<grid(T_, DH_, B_*H_), 256>>>(
        sc, T_, 1, (long long)H_*T_*T_, (long long)T_*T_,
        v,  C_, 1, (long long)T_*C_, DH_,
        o,  C_, 1, (long long)T_*C_, DH_,
        T_, DH_, T_, H_, nullptr, nullptr, 0);

    // x1 = x + o @ Wo + bo   -> d_out
    gemm_kernel<BM,BN,BK,TM,TN><<<grid(BT_, C_, 1), 256>>>(
        o, C_, 1, 0, 0,  Wo, C_, 1, 0, 0,  out, C_, 1, 0, 0,
        BT_, C_, C_, 1, bo, x, 0);

    // LN2
    ln_kernel<<<BT_, 256>>>(out, g2, be2, h2);

    // ff = relu(h2 @ W1 + b1)
    gemm_kernel<BM,BN,BK,TM,TN><<<grid(BT_, FF_, 1), 256>>>(
        h2, C_, 1, 0, 0,  W1, FF_, 1, 0, 0,  ff, FF_, 1, 0, 0,
        BT_, FF_, C_, 1, b1, nullptr, 1);

    // out = x1 + ff @ W2 + b2
    gemm_kernel<BM,BN,BK,TM,TN><<<grid(BT_, C_, 1), 256>>>(
        ff, FF_, 1, 0, 0,  W2, C_, 1, 0, 0,  out, C_, 1, 0, 0,
        BT_, C_, FF_, 1, b2, out, 0);
}

// round 2
// speedup vs baseline: 1.2663x; 1.2663x over previous
#include <cuda_runtime.h>
#include <math.h>
#include <stdint.h>

#define B_  2
#define T_  2048
#define C_  1024
#define H_  16
#define DH_ 64
#define BT_ (B_*T_)
#define FF_ (4*C_)

// ------------------- device scratch (no allocations allowed) -------------------
__device__ float g_h  [BT_*C_];
__device__ float g_q  [BT_*C_];
__device__ float g_k  [BT_*C_];
__device__ float g_v  [BT_*C_];
__device__ float g_o  [BT_*C_];
__device__ float g_h2 [BT_*C_];
__device__ float g_ff [BT_*FF_];
__device__ float g_sc [(size_t)B_*H_*T_*T_];   // 536 MB scores
__device__ float g_Wqp[C_*C_];
__device__ float g_Wkp[C_*C_];
__device__ float g_Wvp[C_*C_];

// ------------------- block reductions -------------------
__device__ __forceinline__ float block_reduce_sum(float v) {
    __shared__ float sm[8];
    __shared__ float res;
    #pragma unroll
    for (int o = 16; o; o >>= 1) v += __shfl_xor_sync(0xffffffffu, v, o);
    if ((threadIdx.x & 31) == 0) sm[threadIdx.x >> 5] = v;
    __syncthreads();
    if (threadIdx.x < 32) {
        float t = (threadIdx.x < 8) ? sm[threadIdx.x] : 0.f;
        #pragma unroll
        for (int o = 4; o; o >>= 1) t += __shfl_xor_sync(0xffffffffu, t, o);
        if (threadIdx.x == 0) res = t;
    }
    __syncthreads();
    return res;
}

__device__ __forceinline__ float block_reduce_max(float v) {
    __shared__ float sm[8];
    __shared__ float res;
    #pragma unroll
    for (int o = 16; o; o >>= 1) v = fmaxf(v, __shfl_xor_sync(0xffffffffu, v, o));
    if ((threadIdx.x & 31) == 0) sm[threadIdx.x >> 5] = v;
    __syncthreads();
    if (threadIdx.x < 32) {
        float t = (threadIdx.x < 8) ? sm[threadIdx.x] : -3.4e38f;
        #pragma unroll
        for (int o = 4; o; o >>= 1) t = fmaxf(t, __shfl_xor_sync(0xffffffffu, t, o));
        if (threadIdx.x == 0) res = t;
    }
    __syncthreads();
    return res;
}

// ------------------- weight repack: (H, C, Dh) -> (C, H*Dh) -------------------
__global__ void repack_kernel(const float* __restrict__ W, float* __restrict__ out) {
    int idx = blockIdx.x * blockDim.x + threadIdx.x;
    if (idx >= C_ * C_) return;
    int c = idx / C_, n = idx % C_;
    out[idx] = W[((size_t)(n / DH_) * C_ + c) * DH_ + (n % DH_)];
}

// ------------------- layernorm: one block per row of C=1024 -------------------
__global__ void __launch_bounds__(256) ln_kernel(const float* __restrict__ x,
                                                 const float* __restrict__ g,
                                                 const float* __restrict__ b,
                                                 float* __restrict__ out) {
    size_t row = blockIdx.x;
    const float* xr = x + row * C_;
    float v[4]; float s = 0.f;
    #pragma unroll
    for (int i = 0; i < 4; i++) { v[i] = xr[threadIdx.x + i*256]; s += v[i]; }
    float mu = block_reduce_sum(s) * (1.f / C_);
    float s2 = 0.f;
    #pragma unroll
    for (int i = 0; i < 4; i++) { float d = v[i] - mu; s2 += d * d; }
    float rstd = rsqrtf(block_reduce_sum(s2) * (1.f / C_) + 1e-5f);
    float* orow = out + row * C_;
    #pragma unroll
    for (int i = 0; i < 4; i++) {
        int j = threadIdx.x + i*256;
        orow[j] = (v[i] - mu) * rstd * g[j] + b[j];
    }
}

// ------------------- softmax over rows of T=2048 (scale folded in) -------------
__global__ void __launch_bounds__(256) softmax_kernel(float* __restrict__ s) {
    float* r = s + (size_t)blockIdx.x * T_;
    const float scale = 0.03125f;  // C^-0.5 = 1/32
    float v[8]; float mx = -3.4e38f;
    #pragma unroll
    for (int i = 0; i < 8; i++) { v[i] = r[threadIdx.x + i*256] * scale; mx = fmaxf(mx, v[i]); }
    mx = block_reduce_max(mx);
    float sum = 0.f;
    #pragma unroll
    for (int i = 0; i < 8; i++) { v[i] = __expf(v[i] - mx); sum += v[i]; }
    float inv = 1.f / block_reduce_sum(sum);
    #pragma unroll
    for (int i = 0; i < 8; i++) r[threadIdx.x + i*256] = v[i] * inv;
}

// ------------------- tf32 helpers -------------------
__device__ __forceinline__ float to_tf32(float x) {
    uint32_t u;
    asm("cvt.rna.tf32.f32 %0, %1;" : "=r"(u) : "f"(x));
    return __uint_as_float(u);
}

__device__ __forceinline__ void mma_tf32(float* c, const uint32_t* a, const uint32_t* b) {
    asm volatile(
        "mma.sync.aligned.m16n8k8.row.col.f32.tf32.tf32.f32 "
        "{%0,%1,%2,%3}, {%4,%5,%6,%7}, {%8,%9}, {%0,%1,%2,%3};"
        : "+f"(c[0]), "+f"(c[1]), "+f"(c[2]), "+f"(c[3])
        : "r"(a[0]), "r"(a[1]), "r"(a[2]), "r"(a[3]), "r"(b[0]), "r"(b[1]));
}

// ------------------- tf32 tensor-core strided batched GEMM ----------------------
// C[m,n] = sum_k A[m,k]*B[k,n] (+bias[n]) (+resid) (relu)
// 256 threads = 8 warps arranged WGM x WGN; warp tile WM x WN; mma m16n8k8.
template<int BM, int BN, int WGM, int WGN>
__global__ void __launch_bounds__(256)
mma_gemm(const float* __restrict__ A, long long rsA, long long csA, long long sAb, long long sAh,
         const float* __restrict__ B, long long rsB, long long csB, long long sBb, long long sBh,
         float* C, long long rsC, long long csC, long long sCb, long long sCh,
         int M, int N, int K, int Hdim,
         const float* __restrict__ bias,
         const float* resid, int relu) {
    constexpr int THREADS = 256;
    constexpr int BK = 16;
    constexpr int WM = BM / WGM;     // rows per warp
    constexpr int WN = BN / WGN;     // cols per warp
    constexpr int MT = WM / 16;      // m16 tiles per warp
    constexpr int NT = WN / 8;       // n8 tiles per warp
    static_assert(WGM * WGN == 8, "8 warps");

    __shared__ float As[BM][BK + 4];   // [m][k] : frag addr m*20+k -> conflict-free
    __shared__ float Bs[BN][BK + 4];   // [n][k]

    int z = blockIdx.z;
    int bb = z / Hdim, hh = z % Hdim;
    A += bb * sAb + hh * sAh;
    B += bb * sBb + hh * sBh;
    C += bb * sCb + hh * sCh;
    if (resid) resid += bb * sCb + hh * sCh;

    int tid  = threadIdx.x;
    int wid  = tid >> 5;
    int lane = tid & 31;
    int g    = lane >> 2;      // groupID
    int tq   = lane & 3;       // threadID in group
    int wm0  = (wid % WGM) * WM;
    int wn0  = (wid / WGM) * WN;
    int row0 = blockIdx.y * BM;
    int col0 = blockIdx.x * BN;

    float acc[MT][NT][4];
    #pragma unroll
    for (int i = 0; i < MT; i++)
        #pragma unroll
        for (int j = 0; j < NT; j++)
            #pragma unroll
            for (int r = 0; r < 4; r++) acc[i][j][r] = 0.f;

    for (int k0 = 0; k0 < K; k0 += BK) {
        // ---- stage A tile ----
        if (csA == 1) {
            #pragma unroll
            for (int l = tid; l < BM * 4; l += THREADS) {
                int m = l >> 2, k4 = (l & 3) << 2;
                const float4 f = *reinterpret_cast<const float4*>(
                    &A[(size_t)(row0 + m) * rsA + (size_t)k0 + k4]);
                As[m][k4+0] = to_tf32(f.x); As[m][k4+1] = to_tf32(f.y);
                As[m][k4+2] = to_tf32(f.z); As[m][k4+3] = to_tf32(f.w);
            }
        } else {
            #pragma unroll
            for (int l = tid; l < BM * BK; l += THREADS) {
                int m = l % BM, kk = l / BM;
                As[m][kk] = to_tf32(A[(size_t)(row0 + m) * rsA + (size_t)(k0 + kk) * csA]);
            }
        }
        // ---- stage B tile ----
        if (csB == 1) {
            #pragma unroll
            for (int l = tid; l < BN * 4; l += THREADS) {
                int n4 = (l % (BN/4)) << 2, kk = l / (BN/4);
                const float4 f = *reinterpret_cast<const float4*>(
                    &B[(size_t)(k0 + kk) * rsB + (size_t)(col0 + n4)]);
                Bs[n4+0][kk] = to_tf32(f.x); Bs[n4+1][kk] = to_tf32(f.y);
                Bs[n4+2][kk] = to_tf32(f.z); Bs[n4+3][kk] = to_tf32(f.w);
            }
        } else if (rsB == 1) {
            #pragma unroll
            for (int l = tid; l < BN * 4; l += THREADS) {
                int k4 = (l & 3) << 2, n = l >> 2;
                const float4 f = *reinterpret_cast<const float4*>(
                    &B[(size_t)k0 + k4 + (size_t)(col0 + n) * csB]);
                Bs[n][k4+0] = to_tf32(f.x); Bs[n][k4+1] = to_tf32(f.y);
                Bs[n][k4+2] = to_tf32(f.z); Bs[n][k4+3] = to_tf32(f.w);
            }
        } else {
            #pragma unroll
            for (int l = tid; l < BN * BK; l += THREADS) {
                int kk = l % BK, n = l / BK;
                Bs[n][kk] = to_tf32(B[(size_t)(k0 + kk) * rsB + (size_t)(col0 + n) * csB]);
            }
        }
        __syncthreads();

        // ---- compute: two k8 steps ----
        #pragma unroll
        for (int ks = 0; ks < 2; ks++) {
            uint32_t a[MT][4], b[NT][2];
            int kb = ks * 8;
            #pragma unroll
            for (int mt = 0; mt < MT; mt++) {
                int mr = wm0 + mt * 16;
                a[mt][0] = __float_as_uint(As[mr + g    ][kb + tq    ]);
                a[mt][1] = __float_as_uint(As[mr + g + 8][kb + tq    ]);
                a[mt][2] = __float_as_uint(As[mr + g    ][kb + tq + 4]);
                a[mt][3] = __float_as_uint(As[mr + g + 8][kb + tq + 4]);
            }
            #pragma unroll
            for (int nt = 0; nt < NT; nt++) {
                int nr = wn0 + nt * 8;
                b[nt][0] = __float_as_uint(Bs[nr + g][kb + tq    ]);
                b[nt][1] = __float_as_uint(Bs[nr + g][kb + tq + 4]);
            }
            #pragma unroll
            for (int mt = 0; mt < MT; mt++)
                #pragma unroll
                for (int nt = 0; nt < NT; nt++)
                    mma_tf32(acc[mt][nt], a[mt], b[nt]);
        }
        __syncthreads();
    }

    // ---- epilogue ----
    #pragma unroll
    for (int mt = 0; mt < MT; mt++) {
        #pragma unroll
        for (int nt = 0; nt < NT; nt++) {
            #pragma unroll
            for (int r = 0; r < 4; r++) {
                int m = row0 + wm0 + mt * 16 + g + ((r >= 2) ? 8 : 0);
                int n = col0 + wn0 + nt * 8 + 2 * tq + (r & 1);
                float val = acc[mt][nt][r];
                if (bias)  val += bias[n];
                size_t ci = (size_t)m * rsC + (size_t)n * csC;
                if (resid) val += resid[ci];
                if (relu)  val = fmaxf(val, 0.f);
                C[ci] = val;
            }
        }
    }
}

// ------------------- launcher ---------------------------------------------------
extern "C" void kernel_launch(void* const* d_in, const int* in_sizes, int n_in,
                              void* d_out, int out_size) {
    const float* x   = (const float*)d_in[0];
    const float* Wq  = (const float*)d_in[1];
    const float* Wk  = (const float*)d_in[2];
    const float* Wv  = (const float*)d_in[3];
    const float* Wo  = (const float*)d_in[4];
    const float* bo  = (const float*)d_in[5];
    const float* W1  = (const float*)d_in[6];
    const float* b1  = (const float*)d_in[7];
    const float* W2  = (const float*)d_in[8];
    const float* b2  = (const float*)d_in[9];
    const float* g1  = (const float*)d_in[10];
    const float* be1 = (const float*)d_in[11];
    const float* g2  = (const float*)d_in[12];
    const float* be2 = (const float*)d_in[13];
    float* out = (float*)d_out;

    float *h, *q, *k, *v, *o, *h2, *ff, *sc, *wqp, *wkp, *wvp;
    cudaGetSymbolAddress((void**)&h,   g_h);
    cudaGetSymbolAddress((void**)&q,   g_q);
    cudaGetSymbolAddress((void**)&k,   g_k);
    cudaGetSymbolAddress((void**)&v,   g_v);
    cudaGetSymbolAddress((void**)&o,   g_o);
    cudaGetSymbolAddress((void**)&h2,  g_h2);
    cudaGetSymbolAddress((void**)&ff,  g_ff);
    cudaGetSymbolAddress((void**)&sc,  g_sc);
    cudaGetSymbolAddress((void**)&wqp, g_Wqp);
    cudaGetSymbolAddress((void**)&wkp, g_Wkp);
    cudaGetSymbolAddress((void**)&wvp, g_Wvp);

    // repack per-head projection weights to (C, H*Dh)
    repack_kernel<<<(C_*C_ + 255)/256, 256>>>(Wq, wqp);
    repack_kernel<<<(C_*C_ + 255)/256, 256>>>(Wk, wkp);
    repack_kernel<<<(C_*C_ + 255)/256, 256>>>(Wv, wvp);

    // LN1
    ln_kernel<<<BT_, 256>>>(x, g1, be1, h);

    // q/k/v = h @ Wp   (BT x C) @ (C x C)
    dim3 gQKV(C_/128, BT_/128, 1);
    mma_gemm<128,128,4,2><<<gQKV, 256>>>(
        h, C_, 1, 0, 0,  wqp, C_, 1, 0, 0,  q, C_, 1, 0, 0,
        BT_, C_, C_, 1, nullptr, nullptr, 0);
    mma_gemm<128,128,4,2><<<gQKV, 256>>>(
        h, C_, 1, 0, 0,  wkp, C_, 1, 0, 0,  k, C_, 1, 0, 0,
        BT_, C_, C_, 1, nullptr, nullptr, 0);
    mma_gemm<128,128,4,2><<<gQKV, 256>>>(
        h, C_, 1, 0, 0,  wvp, C_, 1, 0, 0,  v, C_, 1, 0, 0,
        BT_, C_, C_, 1, nullptr, nullptr, 0);

    // scores[b,h] = q[b,h] (T x Dh) @ k[b,h]^T (Dh x T)
    mma_gemm<128,128,4,2><<<dim3(T_/128, T_/128, B_*H_), 256>>>(
        q,  C_, 1, (long long)T_*C_, DH_,
        k,  1, C_, (long long)T_*C_, DH_,
        sc, T_, 1, (long long)H_*T_*T_, (long long)T_*T_,
        T_, T_, DH_, H_, nullptr, nullptr, 0);

    // softmax (scale 1/32 folded in)
    softmax_kernel<<<B_*H_*T_, 256>>>(sc);

    // o[b,h] = P (T x T) @ v[b,h] (T x Dh)
    mma_gemm<128,64,4,2><<<dim3(1, T_/128, B_*H_), 256>>>(
        sc, T_, 1, (long long)H_*T_*T_, (long long)T_*T_,
        v,  C_, 1, (long long)T_*C_, DH_,
        o,  C_, 1, (long long)T_*C_, DH_,
        T_, DH_, T_, H_, nullptr, nullptr, 0);

    // x1 = x + o @ Wo + bo   -> d_out
    mma_gemm<128,128,4,2><<<gQKV, 256>>>(
        o, C_, 1, 0, 0,  Wo, C_, 1, 0, 0,  out, C_, 1, 0, 0,
        BT_, C_, C_, 1, bo, x, 0);

    // LN2
    ln_kernel<<<BT_, 256>>>(out, g2, be2, h2);

    // ff = relu(h2 @ W1 + b1)
    mma_gemm<128,128,4,2><<<dim3(FF_/128, BT_/128, 1), 256>>>(
        h2, C_, 1, 0, 0,  W1, FF_, 1, 0, 0,  ff, FF_, 1, 0, 0,
        BT_, FF_, C_, 1, b1, nullptr, 1);

    // out = x1 + ff @ W2 + b2
    mma_gemm<128,128,4,2><<<gQKV, 256>>>(
        ff, FF_, 1, 0, 0,  W2, C_, 1, 0, 0,  out, C_, 1, 0, 0,
        BT_, C_, FF_, 1, b2, out, 0);
}

// round 3
// speedup vs baseline: 1.9924x; 1.5734x over previous
#include <cuda_runtime.h>
#include <math.h>
#include <stdint.h>

#define B_  2
#define T_  2048
#define C_  1024
#define H_  16
#define DH_ 64
#define BT_ (B_*T_)
#define FF_ (4*C_)
#define S3_ (3*C_)
#define LOG2E 1.4426950408889634f

// ------------------- device scratch (no allocations allowed) -------------------
__device__ float g_h   [BT_*C_];
__device__ float g_qkv [(size_t)BT_*S3_];
__device__ float g_o   [BT_*C_];
__device__ float g_h2  [BT_*C_];
__device__ float g_ff  [(size_t)BT_*FF_];
__device__ float g_Wqkv[(size_t)C_*S3_];

// ------------------- block reductions -------------------
__device__ __forceinline__ float block_reduce_sum(float v) {
    __shared__ float sm[8];
    __shared__ float res;
    #pragma unroll
    for (int o = 16; o; o >>= 1) v += __shfl_xor_sync(0xffffffffu, v, o);
    if ((threadIdx.x & 31) == 0) sm[threadIdx.x >> 5] = v;
    __syncthreads();
    if (threadIdx.x < 32) {
        float t = (threadIdx.x < 8) ? sm[threadIdx.x] : 0.f;
        #pragma unroll
        for (int o = 4; o; o >>= 1) t += __shfl_xor_sync(0xffffffffu, t, o);
        if (threadIdx.x == 0) res = t;
    }
    __syncthreads();
    return res;
}

// ------------------- weight repack: 3 x (H, C, Dh) -> (C, 3C) -------------------
__global__ void repack_qkv_kernel(const float* __restrict__ Wq,
                                  const float* __restrict__ Wk,
                                  const float* __restrict__ Wv,
                                  float* __restrict__ out) {
    int idx = blockIdx.x * blockDim.x + threadIdx.x;
    if (idx >= C_ * S3_) return;
    int c = idx / S3_, n = idx % S3_;
    const float* W = (n < C_) ? Wq : ((n < 2*C_) ? Wk : Wv);
    int nn = n % C_;
    out[idx] = W[((size_t)(nn / DH_) * C_ + c) * DH_ + (nn % DH_)];
}

// ------------------- layernorm -------------------
__global__ void __launch_bounds__(256) ln_kernel(const float* __restrict__ x,
                                                 const float* __restrict__ g,
                                                 const float* __restrict__ b,
                                                 float* __restrict__ out) {
    size_t row = blockIdx.x;
    const float* xr = x + row * C_;
    float v[4]; float s = 0.f;
    #pragma unroll
    for (int i = 0; i < 4; i++) { v[i] = xr[threadIdx.x + i*256]; s += v[i]; }
    float mu = block_reduce_sum(s) * (1.f / C_);
    float s2 = 0.f;
    #pragma unroll
    for (int i = 0; i < 4; i++) { float d = v[i] - mu; s2 += d * d; }
    float rstd = rsqrtf(block_reduce_sum(s2) * (1.f / C_) + 1e-5f);
    float* orow = out + row * C_;
    #pragma unroll
    for (int i = 0; i < 4; i++) {
        int j = threadIdx.x + i*256;
        orow[j] = (v[i] - mu) * rstd * g[j] + b[j];
    }
}

// ------------------- tf32 helpers -------------------
__device__ __forceinline__ float to_tf32(float x) {
    uint32_t u;
    asm("cvt.rna.tf32.f32 %0, %1;" : "=r"(u) : "f"(x));
    return __uint_as_float(u);
}

__device__ __forceinline__ void mma_tf32(float* c, const uint32_t* a, const uint32_t* b) {
    asm volatile(
        "mma.sync.aligned.m16n8k8.row.col.f32.tf32.tf32.f32 "
        "{%0,%1,%2,%3}, {%4,%5,%6,%7}, {%8,%9}, {%0,%1,%2,%3};"
        : "+f"(c[0]), "+f"(c[1]), "+f"(c[2]), "+f"(c[3])
        : "r"(a[0]), "r"(a[1]), "r"(a[2]), "r"(a[3]), "r"(b[0]), "r"(b[1]));
}

// ------------------- fused flash attention ------------------------------------
// grid (T/128, B*H), 256 threads = 8 warps; warp w owns q-rows [16w,16w+16).
// qkv layout: (b, t, [q|k|v] interleaved 3C), head offset h*64.
// out: (b, t, h, d) row stride C.
__global__ void __launch_bounds__(256) flash_kernel(const float* __restrict__ qkv,
                                                    float* __restrict__ o) {
    extern __shared__ float sm[];
    float* Qs = sm;                  // [128][68]
    float* Ks = Qs + 128*68;         // [128][68]
    float* Vs = Ks + 128*68;         // [64][132]   Vs[d][key]
    float* Ps = Vs + 64*132;         // [128][132]  Ps[qrow][key]

    int bh = blockIdx.y, bb = bh >> 4, hh = bh & 15;
    int q0 = blockIdx.x * 128;
    const float* qb = qkv + (size_t)(bb*T_ + q0)*S3_ + hh*DH_;
    const float* kb = qkv + (size_t)bb*T_*S3_ + C_   + hh*DH_;
    const float* vb = qkv + (size_t)bb*T_*S3_ + 2*C_ + hh*DH_;

    int tid = threadIdx.x, wid = tid >> 5, lane = tid & 31;
    int g = lane >> 2, tq = lane & 3;
    int wm0 = wid * 16;

    // stage Q once (scale 1/32 folded in; exact, power of 2)
    #pragma unroll
    for (int l = tid; l < 2048; l += 256) {
        int m = l >> 4, d4 = (l & 15) << 2;
        float4 f = *reinterpret_cast<const float4*>(qb + (size_t)m*S3_ + d4);
        Qs[m*68+d4+0] = to_tf32(f.x*0.03125f);
        Qs[m*68+d4+1] = to_tf32(f.y*0.03125f);
        Qs[m*68+d4+2] = to_tf32(f.z*0.03125f);
        Qs[m*68+d4+3] = to_tf32(f.w*0.03125f);
    }

    float mrow[2] = {-1e30f, -1e30f};
    float lrow[2] = {0.f, 0.f};
    float acc_o[8][4];
    #pragma unroll
    for (int dt = 0; dt < 8; dt++)
        #pragma unroll
        for (int r = 0; r < 4; r++) acc_o[dt][r] = 0.f;

    for (int n0 = 0; n0 < T_; n0 += 128) {
        __syncthreads();   // Q staged (iter 0); K/V readers of prev iter done
        #pragma unroll
        for (int l = tid; l < 2048; l += 256) {
            int n = l >> 4, d4 = (l & 15) << 2;
            float4 f = *reinterpret_cast<const float4*>(kb + (size_t)(n0+n)*S3_ + d4);
            Ks[n*68+d4+0] = to_tf32(f.x);
            Ks[n*68+d4+1] = to_tf32(f.y);
            Ks[n*68+d4+2] = to_tf32(f.z);
            Ks[n*68+d4+3] = to_tf32(f.w);
        }
        #pragma unroll
        for (int l = tid; l < 8192; l += 256) {
            int d = l & 63, n = l >> 6;
            Vs[d*132 + n] = to_tf32(vb[(size_t)(n0+n)*S3_ + d]);
        }
        __syncthreads();

        // ---- S = Q K^T (warp rows x 128 keys) ----
        float s[16][4];
        #pragma unroll
        for (int nt = 0; nt < 16; nt++) { s[nt][0]=0.f; s[nt][1]=0.f; s[nt][2]=0.f; s[nt][3]=0.f; }
        #pragma unroll
        for (int ks = 0; ks < 8; ks++) {
            int kk = ks * 8;
            uint32_t a[4];
            a[0] = __float_as_uint(Qs[(wm0+g  )*68 + kk + tq    ]);
            a[1] = __float_as_uint(Qs[(wm0+g+8)*68 + kk + tq    ]);
            a[2] = __float_as_uint(Qs[(wm0+g  )*68 + kk + tq + 4]);
            a[3] = __float_as_uint(Qs[(wm0+g+8)*68 + kk + tq + 4]);
            #pragma unroll
            for (int nt = 0; nt < 16; nt++) {
                uint32_t b[2];
                b[0] = __float_as_uint(Ks[(nt*8+g)*68 + kk + tq    ]);
                b[1] = __float_as_uint(Ks[(nt*8+g)*68 + kk + tq + 4]);
                mma_tf32(s[nt], a, b);
            }
        }

        // ---- online softmax (warp-local rows g, g+8) ----
        float mx0 = mrow[0], mx1 = mrow[1];
        #pragma unroll
        for (int nt = 0; nt < 16; nt++) {
            mx0 = fmaxf(mx0, fmaxf(s[nt][0], s[nt][1]));
            mx1 = fmaxf(mx1, fmaxf(s[nt][2], s[nt][3]));
        }
        mx0 = fmaxf(mx0, __shfl_xor_sync(0xffffffffu, mx0, 1));
        mx0 = fmaxf(mx0, __shfl_xor_sync(0xffffffffu, mx0, 2));
        mx1 = fmaxf(mx1, __shfl_xor_sync(0xffffffffu, mx1, 1));
        mx1 = fmaxf(mx1, __shfl_xor_sync(0xffffffffu, mx1, 2));
        float cf0 = exp2f((mrow[0]-mx0)*LOG2E);
        float cf1 = exp2f((mrow[1]-mx1)*LOG2E);
        mrow[0] = mx0; mrow[1] = mx1;

        float sum0 = 0.f, sum1 = 0.f;
        #pragma unroll
        for (int nt = 0; nt < 16; nt++) {
            float p0 = exp2f((s[nt][0]-mx0)*LOG2E);
            float p1 = exp2f((s[nt][1]-mx0)*LOG2E);
            float p2 = exp2f((s[nt][2]-mx1)*LOG2E);
            float p3 = exp2f((s[nt][3]-mx1)*LOG2E);
            sum0 += p0 + p1; sum1 += p2 + p3;
            int col = nt*8 + 2*tq;
            Ps[(wm0+g  )*132 + col    ] = to_tf32(p0);
            Ps[(wm0+g  )*132 + col + 1] = to_tf32(p1);
            Ps[(wm0+g+8)*132 + col    ] = to_tf32(p2);
            Ps[(wm0+g+8)*132 + col + 1] = to_tf32(p3);
        }
        sum0 += __shfl_xor_sync(0xffffffffu, sum0, 1);
        sum0 += __shfl_xor_sync(0xffffffffu, sum0, 2);
        sum1 += __shfl_xor_sync(0xffffffffu, sum1, 1);
        sum1 += __shfl_xor_sync(0xffffffffu, sum1, 2);
        lrow[0] = lrow[0]*cf0 + sum0;
        lrow[1] = lrow[1]*cf1 + sum1;
        #pragma unroll
        for (int dt = 0; dt < 8; dt++) {
            acc_o[dt][0] *= cf0; acc_o[dt][1] *= cf0;
            acc_o[dt][2] *= cf1; acc_o[dt][3] *= cf1;
        }
        __syncwarp();   // Ps writes visible to warp before A-frag reads

        // ---- O += P V ----
        #pragma unroll
        for (int ks = 0; ks < 16; ks++) {
            int kk = ks * 8;
            uint32_t a[4];
            a[0] = __float_as_uint(Ps[(wm0+g  )*132 + kk + tq    ]);
            a[1] = __float_as_uint(Ps[(wm0+g+8)*132 + kk + tq    ]);
            a[2] = __float_as_uint(Ps[(wm0+g  )*132 + kk + tq + 4]);
            a[3] = __float_as_uint(Ps[(wm0+g+8)*132 + kk + tq + 4]);
            #pragma unroll
            for (int dt = 0; dt < 8; dt++) {
                uint32_t b[2];
                b[0] = __float_as_uint(Vs[(dt*8+g)*132 + kk + tq    ]);
                b[1] = __float_as_uint(Vs[(dt*8+g)*132 + kk + tq + 4]);
                mma_tf32(acc_o[dt], a, b);
            }
        }
    }

    float inv0 = 1.f / lrow[0], inv1 = 1.f / lrow[1];
    size_t r0 = (size_t)(bb*T_ + q0 + wm0 + g) * C_ + hh*DH_;
    size_t r1 = r0 + (size_t)8 * C_;
    #pragma unroll
    for (int dt = 0; dt < 8; dt++) {
        int col = dt*8 + 2*tq;
        o[r0 + col    ] = acc_o[dt][0] * inv0;
        o[r0 + col + 1] = acc_o[dt][1] * inv0;
        o[r1 + col    ] = acc_o[dt][2] * inv1;
        o[r1 + col + 1] = acc_o[dt][3] * inv1;
    }
}

// ------------------- tf32 tensor-core GEMM (projections / MLP) ------------------
template<int BM, int BN, int WGM, int WGN>
__global__ void __launch_bounds__(256)
mma_gemm(const float* __restrict__ A, long long rsA, long long csA,
         const float* __restrict__ B, long long rsB, long long csB,
         float* C, long long rsC,
         int M, int N, int K,
         const float* __restrict__ bias,
         const float* resid, int relu) {
    constexpr int THREADS = 256;
    constexpr int BK = 16;
    constexpr int WM = BM / WGM;
    constexpr int WN = BN / WGN;
    constexpr int MT = WM / 16;
    constexpr int NT = WN / 8;
    static_assert(WGM * WGN == 8, "8 warps");

    __shared__ float As[BM][BK + 4];
    __shared__ float Bs[BN][BK + 4];

    int tid  = threadIdx.x;
    int wid  = tid >> 5;
    int lane = tid & 31;
    int g    = lane >> 2;
    int tq   = lane & 3;
    int wm0  = (wid % WGM) * WM;
    int wn0  = (wid / WGM) * WN;
    int row0 = blockIdx.y * BM;
    int col0 = blockIdx.x * BN;

    float acc[MT][NT][4];
    #pragma unroll
    for (int i = 0; i < MT; i++)
        #pragma unroll
        for (int j = 0; j < NT; j++)
            #pragma unroll
            for (int r = 0; r < 4; r++) acc[i][j][r] = 0.f;

    for (int k0 = 0; k0 < K; k0 += BK) {
        // A tile (csA==1 always here)
        #pragma unroll
        for (int l = tid; l < BM * 4; l += THREADS) {
            int m = l >> 2, k4 = (l & 3) << 2;
            const float4 f = *reinterpret_cast<const float4*>(
                &A[(size_t)(row0 + m) * rsA + (size_t)k0 + k4]);
            As[m][k4+0] = to_tf32(f.x); As[m][k4+1] = to_tf32(f.y);
            As[m][k4+2] = to_tf32(f.z); As[m][k4+3] = to_tf32(f.w);
        }
        // B tile (csB==1: row-major K x N)
        #pragma unroll
        for (int l = tid; l < BN * 4; l += THREADS) {
            int n4 = (l % (BN/4)) << 2, kk = l / (BN/4);
            const float4 f = *reinterpret_cast<const float4*>(
                &B[(size_t)(k0 + kk) * rsB + (size_t)(col0 + n4)]);
            Bs[n4+0][kk] = to_tf32(f.x); Bs[n4+1][kk] = to_tf32(f.y);
            Bs[n4+2][kk] = to_tf32(f.z); Bs[n4+3][kk] = to_tf32(f.w);
        }
        __syncthreads();

        #pragma unroll
        for (int ks = 0; ks < 2; ks++) {
            uint32_t a[MT][4], b[NT][2];
            int kb = ks * 8;
            #pragma unroll
            for (int mt = 0; mt < MT; mt++) {
                int mr = wm0 + mt * 16;
                a[mt][0] = __float_as_uint(As[mr + g    ][kb + tq    ]);
                a[mt][1] = __float_as_uint(As[mr + g + 8][kb + tq    ]);
                a[mt][2] = __float_as_uint(As[mr + g    ][kb + tq + 4]);
                a[mt][3] = __float_as_uint(As[mr + g + 8][kb + tq + 4]);
            }
            #pragma unroll
            for (int nt = 0; nt < NT; nt++) {
                int nr = wn0 + nt * 8;
                b[nt][0] = __float_as_uint(Bs[nr + g][kb + tq    ]);
                b[nt][1] = __float_as_uint(Bs[nr + g][kb + tq + 4]);
            }
            #pragma unroll
            for (int mt = 0; mt < MT; mt++)
                #pragma unroll
                for (int nt = 0; nt < NT; nt++)
                    mma_tf32(acc[mt][nt], a[mt], b[nt]);
        }
        __syncthreads();
    }

    #pragma unroll
    for (int mt = 0; mt < MT; mt++) {
        #pragma unroll
        for (int nt = 0; nt < NT; nt++) {
            #pragma unroll
            for (int r = 0; r < 4; r++) {
                int m = row0 + wm0 + mt * 16 + g + ((r >= 2) ? 8 : 0);
                int n = col0 + wn0 + nt * 8 + 2 * tq + (r & 1);
                float val = acc[mt][nt][r];
                if (bias)  val += bias[n];
                size_t ci = (size_t)m * rsC + (size_t)n;
                if (resid) val += resid[ci];
                if (relu)  val = fmaxf(val, 0.f);
                C[ci] = val;
            }
        }
    }
}

// ------------------- launcher ---------------------------------------------------
extern "C" void kernel_launch(void* const* d_in, const int* in_sizes, int n_in,
                              void* d_out, int out_size) {
    const float* x   = (const float*)d_in[0];
    const float* Wq  = (const float*)d_in[1];
    const float* Wk  = (const float*)d_in[2];
    const float* Wv  = (const float*)d_in[3];
    const float* Wo  = (const float*)d_in[4];
    const float* bo  = (const float*)d_in[5];
    const float* W1  = (const float*)d_in[6];
    const float* b1  = (const float*)d_in[7];
    const float* W2  = (const float*)d_in[8];
    const float* b2  = (const float*)d_in[9];
    const float* g1  = (const float*)d_in[10];
    const float* be1 = (const float*)d_in[11];
    const float* g2  = (const float*)d_in[12];
    const float* be2 = (const float*)d_in[13];
    float* out = (float*)d_out;

    float *h, *qkv, *o, *h2, *ff, *wqkv;
    cudaGetSymbolAddress((void**)&h,    g_h);
    cudaGetSymbolAddress((void**)&qkv,  g_qkv);
    cudaGetSymbolAddress((void**)&o,    g_o);
    cudaGetSymbolAddress((void**)&h2,   g_h2);
    cudaGetSymbolAddress((void**)&ff,   g_ff);
    cudaGetSymbolAddress((void**)&wqkv, g_Wqkv);

    static int smem_set = 0;
    const int FLASH_SMEM = (128*68 + 128*68 + 64*132 + 128*132) * 4;
    if (!smem_set) {
        cudaFuncSetAttribute(flash_kernel,
                             cudaFuncAttributeMaxDynamicSharedMemorySize, FLASH_SMEM);
        smem_set = 1;
    }

    // packed QKV weights: (C, 3C)
    repack_qkv_kernel<<<(C_*S3_ + 255)/256, 256>>>(Wq, Wk, Wv, wqkv);

    // LN1
    ln_kernel<<<BT_, 256>>>(x, g1, be1, h);

    // qkv = h @ Wqkv   (BT x 3C)
    mma_gemm<128,128,4,2><<<dim3(S3_/128, BT_/128, 1), 256>>>(
        h, C_, 1,  wqkv, S3_, 1,  qkv, S3_,
        BT_, S3_, C_, nullptr, nullptr, 0);

    // fused attention -> o (b,t,h,d)
    flash_kernel<<<dim3(T_/128, B_*H_), 256, FLASH_SMEM>>>(qkv, o);

    // x1 = x + o @ Wo + bo   -> d_out
    mma_gemm<128,128,4,2><<<dim3(C_/128, BT_/128, 1), 256>>>(
        o, C_, 1,  Wo, C_, 1,  out, C_,
        BT_, C_, C_, bo, x, 0);

    // LN2
    ln_kernel<<<BT_, 256>>>(out, g2, be2, h2);

    // ff = relu(h2 @ W1 + b1)
    mma_gemm<128,128,4,2><<<dim3(FF_/128, BT_/128, 1), 256>>>(
        h2, C_, 1,  W1, FF_, 1,  ff, FF_,
        BT_, FF_, C_, b1, nullptr, 1);

    // out = x1 + ff @ W2 + b2
    mma_gemm<128,128,4,2><<<dim3(C_/128, BT_/128, 1), 256>>>(
        ff, FF_, 1,  W2, C_, 1,  out, C_,
        BT_, C_, FF_, b2, out, 0);
}

// round 4
// speedup vs baseline: 3.7239x; 1.8691x over previous
#include <cuda_runtime.h>
#include <math.h>
#include <stdint.h>

#define B_  2
#define T_  2048
#define C_  1024
#define H_  16
#define DH_ 64
#define BT_ (B_*T_)
#define FF_ (4*C_)
#define S3_ (3*C_)
#define LOG2E 1.4426950408889634f

// ------------------- device scratch (no allocations allowed) -------------------
__device__ float g_h   [BT_*C_];
__device__ float g_qkv [(size_t)BT_*S3_];
__device__ float g_o   [BT_*C_];
__device__ float g_h2  [BT_*C_];
__device__ float g_ff  [(size_t)BT_*FF_];
__device__ float g_Wqkv[(size_t)C_*S3_];
__device__ float g_Wor [(size_t)C_*C_];
__device__ float g_W1r [(size_t)C_*FF_];
__device__ float g_W2r [(size_t)FF_*C_];

// ------------------- tf32 helpers -------------------
__device__ __forceinline__ float to_tf32(float x) {
    uint32_t u;
    asm("cvt.rna.tf32.f32 %0, %1;" : "=r"(u) : "f"(x));
    return __uint_as_float(u);
}
__device__ __forceinline__ uint32_t tf32u(float x) {
    uint32_t u;
    asm("cvt.rna.tf32.f32 %0, %1;" : "=r"(u) : "f"(x));
    return u;
}
__device__ __forceinline__ void mma_tf32(float* c, const uint32_t* a, const uint32_t* b) {
    asm volatile(
        "mma.sync.aligned.m16n8k8.row.col.f32.tf32.tf32.f32 "
        "{%0,%1,%2,%3}, {%4,%5,%6,%7}, {%8,%9}, {%0,%1,%2,%3};"
        : "+f"(c[0]), "+f"(c[1]), "+f"(c[2]), "+f"(c[3])
        : "r"(a[0]), "r"(a[1]), "r"(a[2]), "r"(a[3]), "r"(b[0]), "r"(b[1]));
}
__device__ __forceinline__ void cp16(void* sptr, const void* gptr) {
    uint32_t s = (uint32_t)__cvta_generic_to_shared(sptr);
    asm volatile("cp.async.ca.shared.global [%0], [%1], 16;" :: "r"(s), "l"(gptr));
}
__device__ __forceinline__ void cp_commit() {
    asm volatile("cp.async.commit_group;");
}
template<int N> __device__ __forceinline__ void cp_wait() {
    asm volatile("cp.async.wait_group %0;" :: "n"(N));
}

// ------------------- block reductions -------------------
__device__ __forceinline__ float block_reduce_sum(float v) {
    __shared__ float sm[8];
    __shared__ float res;
    #pragma unroll
    for (int o = 16; o; o >>= 1) v += __shfl_xor_sync(0xffffffffu, v, o);
    if ((threadIdx.x & 31) == 0) sm[threadIdx.x >> 5] = v;
    __syncthreads();
    if (threadIdx.x < 32) {
        float t = (threadIdx.x < 8) ? sm[threadIdx.x] : 0.f;
        #pragma unroll
        for (int o = 4; o; o >>= 1) t += __shfl_xor_sync(0xffffffffu, t, o);
        if (threadIdx.x == 0) res = t;
    }
    __syncthreads();
    return res;
}

// ------------------- weight prep -------------------
__global__ void repack_qkv_kernel(const float* __restrict__ Wq,
                                  const float* __restrict__ Wk,
                                  const float* __restrict__ Wv,
                                  float* __restrict__ out) {
    int idx = blockIdx.x * blockDim.x + threadIdx.x;
    if (idx >= C_ * S3_) return;
    int c = idx / S3_, n = idx % S3_;
    const float* W = (n < C_) ? Wq : ((n < 2*C_) ? Wk : Wv);
    int nn = n % C_;
    out[idx] = to_tf32(W[((size_t)(nn / DH_) * C_ + c) * DH_ + (nn % DH_)]);
}

__global__ void round_copy_kernel(const float* __restrict__ in, float* __restrict__ out, int n4) {
    int i = blockIdx.x * blockDim.x + threadIdx.x;
    if (i >= n4) return;
    float4 f = reinterpret_cast<const float4*>(in)[i];
    f.x = to_tf32(f.x); f.y = to_tf32(f.y); f.z = to_tf32(f.z); f.w = to_tf32(f.w);
    reinterpret_cast<float4*>(out)[i] = f;
}

// ------------------- layernorm (output rounded to tf32) -------------------
__global__ void __launch_bounds__(256) ln_kernel(const float* __restrict__ x,
                                                 const float* __restrict__ g,
                                                 const float* __restrict__ b,
                                                 float* __restrict__ out) {
    size_t row = blockIdx.x;
    const float* xr = x + row * C_;
    float v[4]; float s = 0.f;
    #pragma unroll
    for (int i = 0; i < 4; i++) { v[i] = xr[threadIdx.x + i*256]; s += v[i]; }
    float mu = block_reduce_sum(s) * (1.f / C_);
    float s2 = 0.f;
    #pragma unroll
    for (int i = 0; i < 4; i++) { float d = v[i] - mu; s2 += d * d; }
    float rstd = rsqrtf(block_reduce_sum(s2) * (1.f / C_) + 1e-5f);
    float* orow = out + row * C_;
    #pragma unroll
    for (int i = 0; i < 4; i++) {
        int j = threadIdx.x + i*256;
        orow[j] = to_tf32((v[i] - mu) * rstd * g[j] + b[j]);
    }
}

// ------------------- fused flash attention ------------------------------------
// grid (T/128, B*H), 256 threads = 8 warps; warp w owns q-rows [16w,16w+16).
// qkv pre-rounded tf32. P fed to PV mma via quad shuffles (no smem P).
__global__ void __launch_bounds__(256, 2) flash_kernel(const float* __restrict__ qkv,
                                                       float* __restrict__ o) {
    extern __shared__ float sm[];
    float* Qs = sm;                  // [128][68]
    float* Ks = Qs + 128*68;         // [128][68]
    float* Vs = Ks + 128*68;         // [64][132]   Vs[d][key]

    int bh = blockIdx.y, bb = bh >> 4, hh = bh & 15;
    int q0 = blockIdx.x * 128;
    const float* qb = qkv + (size_t)(bb*T_ + q0)*S3_ + hh*DH_;
    const float* kb = qkv + (size_t)bb*T_*S3_ + C_   + hh*DH_;
    const float* vb = qkv + (size_t)bb*T_*S3_ + 2*C_ + hh*DH_;

    int tid = threadIdx.x, wid = tid >> 5, lane = tid & 31;
    int g = lane >> 2, tq = lane & 3;
    int wm0 = wid * 16;

    // stage Q once; x 2^-5 is exact so values stay tf32
    #pragma unroll
    for (int l = tid; l < 2048; l += 256) {
        int m = l >> 4, d4 = (l & 15) << 2;
        float4 f = *reinterpret_cast<const float4*>(qb + (size_t)m*S3_ + d4);
        Qs[m*68+d4+0] = f.x*0.03125f;
        Qs[m*68+d4+1] = f.y*0.03125f;
        Qs[m*68+d4+2] = f.z*0.03125f;
        Qs[m*68+d4+3] = f.w*0.03125f;
    }

    float mrow[2] = {-1e30f, -1e30f};
    float lrow[2] = {0.f, 0.f};
    float acc_o[8][4];
    #pragma unroll
    for (int dt = 0; dt < 8; dt++)
        #pragma unroll
        for (int r = 0; r < 4; r++) acc_o[dt][r] = 0.f;

    for (int n0 = 0; n0 < T_; n0 += 128) {
        __syncthreads();
        #pragma unroll
        for (int l = tid; l < 2048; l += 256) {
            int n = l >> 4, d4 = (l & 15) << 2;
            float4 f = *reinterpret_cast<const float4*>(kb + (size_t)(n0+n)*S3_ + d4);
            Ks[n*68+d4+0] = f.x;
            Ks[n*68+d4+1] = f.y;
            Ks[n*68+d4+2] = f.z;
            Ks[n*68+d4+3] = f.w;
        }
        #pragma unroll
        for (int l = tid; l < 8192; l += 256) {
            int d = l & 63, n = l >> 6;
            Vs[d*132 + n] = vb[(size_t)(n0+n)*S3_ + d];
        }
        __syncthreads();

        // ---- S = Q K^T ----
        float s[16][4];
        #pragma unroll
        for (int nt = 0; nt < 16; nt++) { s[nt][0]=0.f; s[nt][1]=0.f; s[nt][2]=0.f; s[nt][3]=0.f; }
        #pragma unroll
        for (int ks = 0; ks < 8; ks++) {
            int kk = ks * 8;
            uint32_t a[4];
            a[0] = __float_as_uint(Qs[(wm0+g  )*68 + kk + tq    ]);
            a[1] = __float_as_uint(Qs[(wm0+g+8)*68 + kk + tq    ]);
            a[2] = __float_as_uint(Qs[(wm0+g  )*68 + kk + tq + 4]);
            a[3] = __float_as_uint(Qs[(wm0+g+8)*68 + kk + tq + 4]);
            #pragma unroll
            for (int nt = 0; nt < 16; nt++) {
                uint32_t b[2];
                b[0] = __float_as_uint(Ks[(nt*8+g)*68 + kk + tq    ]);
                b[1] = __float_as_uint(Ks[(nt*8+g)*68 + kk + tq + 4]);
                mma_tf32(s[nt], a, b);
            }
        }

        // ---- online softmax ----
        float mx0 = mrow[0], mx1 = mrow[1];
        #pragma unroll
        for (int nt = 0; nt < 16; nt++) {
            mx0 = fmaxf(mx0, fmaxf(s[nt][0], s[nt][1]));
            mx1 = fmaxf(mx1, fmaxf(s[nt][2], s[nt][3]));
        }
        mx0 = fmaxf(mx0, __shfl_xor_sync(0xffffffffu, mx0, 1));
        mx0 = fmaxf(mx0, __shfl_xor_sync(0xffffffffu, mx0, 2));
        mx1 = fmaxf(mx1, __shfl_xor_sync(0xffffffffu, mx1, 1));
        mx1 = fmaxf(mx1, __shfl_xor_sync(0xffffffffu, mx1, 2));
        float cf0 = exp2f((mrow[0]-mx0)*LOG2E);
        float cf1 = exp2f((mrow[1]-mx1)*LOG2E);
        mrow[0] = mx0; mrow[1] = mx1;
        #pragma unroll
        for (int dt = 0; dt < 8; dt++) {
            acc_o[dt][0] *= cf0; acc_o[dt][1] *= cf0;
            acc_o[dt][2] *= cf1; acc_o[dt][3] *= cf1;
        }

        // ---- P = exp(S - mx); O += P V  (P via quad shuffles, no smem) ----
        float sum0 = 0.f, sum1 = 0.f;
        int src0 = (lane & ~3) | (tq >> 1);
        int src1 = src0 + 2;
        bool odd = (tq & 1);
        #pragma unroll
        for (int ks = 0; ks < 16; ks++) {
            float p0 = exp2f((s[ks][0]-mx0)*LOG2E);
            float p1 = exp2f((s[ks][1]-mx0)*LOG2E);
            float p2 = exp2f((s[ks][2]-mx1)*LOG2E);
            float p3 = exp2f((s[ks][3]-mx1)*LOG2E);
            sum0 += p0 + p1; sum1 += p2 + p3;
            uint32_t u0 = tf32u(p0), u1 = tf32u(p1), u2 = tf32u(p2), u3 = tf32u(p3);
            uint32_t w00 = __shfl_sync(0xffffffffu, u0, src0);
            uint32_t w01 = __shfl_sync(0xffffffffu, u1, src0);
            uint32_t w10 = __shfl_sync(0xffffffffu, u0, src1);
            uint32_t w11 = __shfl_sync(0xffffffffu, u1, src1);
            uint32_t x00 = __shfl_sync(0xffffffffu, u2, src0);
            uint32_t x01 = __shfl_sync(0xffffffffu, u3, src0);
            uint32_t x10 = __shfl_sync(0xffffffffu, u2, src1);
            uint32_t x11 = __shfl_sync(0xffffffffu, u3, src1);
            uint32_t a[4];
            a[0] = odd ? w01 : w00;
            a[2] = odd ? w11 : w10;
            a[1] = odd ? x01 : x00;
            a[3] = odd ? x11 : x10;
            int kk = ks * 8;
            #pragma unroll
            for (int dt = 0; dt < 8; dt++) {
                uint32_t b[2];
                b[0] = __float_as_uint(Vs[(dt*8+g)*132 + kk + tq    ]);
                b[1] = __float_as_uint(Vs[(dt*8+g)*132 + kk + tq + 4]);
                mma_tf32(acc_o[dt], a, b);
            }
        }
        sum0 += __shfl_xor_sync(0xffffffffu, sum0, 1);
        sum0 += __shfl_xor_sync(0xffffffffu, sum0, 2);
        sum1 += __shfl_xor_sync(0xffffffffu, sum1, 1);
        sum1 += __shfl_xor_sync(0xffffffffu, sum1, 2);
        lrow[0] = lrow[0]*cf0 + sum0;
        lrow[1] = lrow[1]*cf1 + sum1;
    }

    float inv0 = 1.f / lrow[0], inv1 = 1.f / lrow[1];
    size_t r0 = (size_t)(bb*T_ + q0 + wm0 + g) * C_ + hh*DH_;
    size_t r1 = r0 + (size_t)8 * C_;
    #pragma unroll
    for (int dt = 0; dt < 8; dt++) {
        int col = dt*8 + 2*tq;
        o[r0 + col    ] = to_tf32(acc_o[dt][0] * inv0);
        o[r0 + col + 1] = to_tf32(acc_o[dt][1] * inv0);
        o[r1 + col    ] = to_tf32(acc_o[dt][2] * inv1);
        o[r1 + col + 1] = to_tf32(acc_o[dt][3] * inv1);
    }
}

// ------------------- tf32 GEMM: cp.async double-buffered ------------------------
// A (M x K) row-major, B (K x N) row-major, both pre-rounded to tf32.
// BM=BN=128, BK=16; 8 warps 4x2; warp tile 32x64; m16n8k8.
__global__ void __launch_bounds__(256)
mma_gemm(const float* __restrict__ A, int lda,
         const float* __restrict__ B, int ldb,
         float* __restrict__ C, int ldc,
         int K,
         const float* __restrict__ bias,
         const float* __restrict__ resid, int relu, int round_out) {
    constexpr int AST = 20;    // A smem row stride (floats)
    constexpr int BST = 136;   // B smem row stride (floats); 136 % 32 == 8 -> conflict-free frags
    __shared__ float As[2][128*AST];
    __shared__ float Bs[2][16*BST];

    int tid  = threadIdx.x;
    int wid  = tid >> 5;
    int lane = tid & 31;
    int g    = lane >> 2;
    int tq   = lane & 3;
    int wm0  = (wid & 3) * 32;          // 4 warps along M
    int wn0  = (wid >> 2) * 64;         // 2 warps along N
    int row0 = blockIdx.y * 128;
    int col0 = blockIdx.x * 128;

    auto stage = [&](int buf, int k0) {
        #pragma unroll
        for (int c = tid; c < 512; c += 256) {          // A: 128 rows x 16 k
            int m = c >> 2, k4 = (c & 3) << 2;
            cp16(&As[buf][m*AST + k4], &A[(size_t)(row0 + m)*lda + k0 + k4]);
        }
        #pragma unroll
        for (int c = tid; c < 512; c += 256) {          // B: 16 k-rows x 128 n
            int kk = c >> 5, n4 = (c & 31) << 2;
            cp16(&Bs[buf][kk*BST + n4], &B[(size_t)(k0 + kk)*ldb + col0 + n4]);
        }
    };

    float acc[2][8][4];
    #pragma unroll
    for (int i = 0; i < 2; i++)
        #pragma unroll
        for (int j = 0; j < 8; j++)
            #pragma unroll
            for (int r = 0; r < 4; r++) acc[i][j][r] = 0.f;

    stage(0, 0);
    cp_commit();

    int NT = K >> 4;
    for (int kt = 0; kt < NT; kt++) {
        if (kt + 1 < NT) {
            stage((kt + 1) & 1, (kt + 1) << 4);
            cp_commit();
            cp_wait<1>();
        } else {
            cp_wait<0>();
        }
        __syncthreads();

        const float* Ab = As[kt & 1];
        const float* Bb = Bs[kt & 1];
        #pragma unroll
        for (int ks = 0; ks < 2; ks++) {
            int kb = ks * 8;
            uint32_t a[2][4], b[8][2];
            #pragma unroll
            for (int mt = 0; mt < 2; mt++) {
                int mr = wm0 + mt*16;
                a[mt][0] = __float_as_uint(Ab[(mr + g    )*AST + kb + tq    ]);
                a[mt][1] = __float_as_uint(Ab[(mr + g + 8)*AST + kb + tq    ]);
                a[mt][2] = __float_as_uint(Ab[(mr + g    )*AST + kb + tq + 4]);
                a[mt][3] = __float_as_uint(Ab[(mr + g + 8)*AST + kb + tq + 4]);
            }
            #pragma unroll
            for (int nt = 0; nt < 8; nt++) {
                int nc = wn0 + nt*8 + g;
                b[nt][0] = __float_as_uint(Bb[(kb + tq    )*BST + nc]);
                b[nt][1] = __float_as_uint(Bb[(kb + tq + 4)*BST + nc]);
            }
            #pragma unroll
            for (int mt = 0; mt < 2; mt++)
                #pragma unroll
                for (int nt = 0; nt < 8; nt++)
                    mma_tf32(acc[mt][nt], a[mt], b[nt]);
        }
        __syncthreads();
    }

    // ---- epilogue (float2 stores) ----
    #pragma unroll
    for (int mt = 0; mt < 2; mt++) {
        int m0 = row0 + wm0 + mt*16 + g;
        #pragma unroll
        for (int nt = 0; nt < 8; nt++) {
            int n = col0 + wn0 + nt*8 + 2*tq;
            float bx = 0.f, by = 0.f;
            if (bias) { bx = bias[n]; by = bias[n+1]; }
            #pragma unroll
            for (int half = 0; half < 2; half++) {
                int m = m0 + half*8;
                float vx = acc[mt][nt][half*2+0] + bx;
                float vy = acc[mt][nt][half*2+1] + by;
                size_t ci = (size_t)m * ldc + n;
                if (resid) {
                    float2 rr = *reinterpret_cast<const float2*>(&resid[ci]);
                    vx += rr.x; vy += rr.y;
                }
                if (relu) { vx = fmaxf(vx, 0.f); vy = fmaxf(vy, 0.f); }
                if (round_out) { vx = to_tf32(vx); vy = to_tf32(vy); }
                float2 vv = make_float2(vx, vy);
                *reinterpret_cast<float2*>(&C[ci]) = vv;
            }
        }
    }
}

// ------------------- launcher ---------------------------------------------------
extern "C" void kernel_launch(void* const* d_in, const int* in_sizes, int n_in,
                              void* d_out, int out_size) {
    const float* x   = (const float*)d_in[0];
    const float* Wq  = (const float*)d_in[1];
    const float* Wk  = (const float*)d_in[2];
    const float* Wv  = (const float*)d_in[3];
    const float* Wo  = (const float*)d_in[4];
    const float* bo  = (const float*)d_in[5];
    const float* W1  = (const float*)d_in[6];
    const float* b1  = (const float*)d_in[7];
    const float* W2  = (const float*)d_in[8];
    const float* b2  = (const float*)d_in[9];
    const float* g1  = (const float*)d_in[10];
    const float* be1 = (const float*)d_in[11];
    const float* g2  = (const float*)d_in[12];
    const float* be2 = (const float*)d_in[13];
    float* out = (float*)d_out;

    float *h, *qkv, *o, *h2, *ff, *wqkv, *wor, *w1r, *w2r;
    cudaGetSymbolAddress((void**)&h,    g_h);
    cudaGetSymbolAddress((void**)&qkv,  g_qkv);
    cudaGetSymbolAddress((void**)&o,    g_o);
    cudaGetSymbolAddress((void**)&h2,   g_h2);
    cudaGetSymbolAddress((void**)&ff,   g_ff);
    cudaGetSymbolAddress((void**)&wqkv, g_Wqkv);
    cudaGetSymbolAddress((void**)&wor,  g_Wor);
    cudaGetSymbolAddress((void**)&w1r,  g_W1r);
    cudaGetSymbolAddress((void**)&w2r,  g_W2r);

    static int smem_set = 0;
    const int FLASH_SMEM = (128*68 + 128*68 + 64*132) * 4;
    if (!smem_set) {
        cudaFuncSetAttribute(flash_kernel,
                             cudaFuncAttributeMaxDynamicSharedMemorySize, FLASH_SMEM);
        smem_set = 1;
    }

    // weight prep (tf32-rounded copies)
    repack_qkv_kernel<<<(C_*S3_ + 255)/256, 256>>>(Wq, Wk, Wv, wqkv);
    round_copy_kernel<<<(C_*C_/4 + 255)/256, 256>>>(Wo, wor, C_*C_/4);
    round_copy_kernel<<<(C_*FF_/4 + 255)/256, 256>>>(W1, w1r, C_*FF_/4);
    round_copy_kernel<<<(FF_*C_/4 + 255)/256, 256>>>(W2, w2r, FF_*C_/4);

    // LN1 (rounded output)
    ln_kernel<<<BT_, 256>>>(x, g1, be1, h);

    // qkv = h @ Wqkv  (rounded output)
    mma_gemm<<<dim3(S3_/128, BT_/128), 256>>>(
        h, C_, wqkv, S3_, qkv, S3_, C_, nullptr, nullptr, 0, 1);

    // fused attention -> o (rounded output)
    flash_kernel<<<dim3(T_/128, B_*H_), 256, FLASH_SMEM>>>(qkv, o);

    // x1 = x + o @ Wo + bo  -> d_out (exact fp32)
    mma_gemm<<<dim3(C_/128, BT_/128), 256>>>(
        o, C_, wor, C_, out, C_, C_, bo, x, 0, 0);

    // LN2 (rounded output)
    ln_kernel<<<BT_, 256>>>(out, g2, be2, h2);

    // ff = relu(h2 @ W1 + b1) (rounded output)
    mma_gemm<<<dim3(FF_/128, BT_/128), 256>>>(
        h2, C_, w1r, FF_, ff, FF_, C_, b1, nullptr, 1, 1);

    // out = x1 + ff @ W2 + b2
    mma_gemm<<<dim3(C_/128, BT_/128), 256>>>(
        ff, FF_, w2r, C_, out, C_, FF_, b2, out, 0, 0);
}

// round 5
// speedup vs baseline: 3.9101x; 1.0500x over previous
#include <cuda_runtime.h>
#include <math.h>
#include <stdint.h>

#define B_  2
#define T_  2048
#define C_  1024
#define H_  16
#define DH_ 64
#define BT_ (B_*T_)
#define FF_ (4*C_)
#define S3_ (3*C_)
#define LOG2E 1.4426950408889634f

// ------------------- device scratch (no allocations allowed) -------------------
__device__ float g_h   [BT_*C_];
__device__ float g_qkv [(size_t)BT_*S3_];
__device__ float g_o   [BT_*C_];
__device__ float g_h2  [BT_*C_];
__device__ float g_ff  [(size_t)BT_*FF_];
__device__ float g_Wqkv[(size_t)C_*S3_];
__device__ float g_Wor [(size_t)C_*C_];
__device__ float g_W1r [(size_t)C_*FF_];
__device__ float g_W2r [(size_t)FF_*C_];

// ------------------- tf32 / async helpers -------------------
__device__ __forceinline__ float to_tf32(float x) {
    uint32_t u;
    asm("cvt.rna.tf32.f32 %0, %1;" : "=r"(u) : "f"(x));
    return __uint_as_float(u);
}
__device__ __forceinline__ uint32_t tf32u(float x) {
    uint32_t u;
    asm("cvt.rna.tf32.f32 %0, %1;" : "=r"(u) : "f"(x));
    return u;
}
__device__ __forceinline__ void mma_tf32(float* c, const uint32_t* a, const uint32_t* b) {
    asm volatile(
        "mma.sync.aligned.m16n8k8.row.col.f32.tf32.tf32.f32 "
        "{%0,%1,%2,%3}, {%4,%5,%6,%7}, {%8,%9}, {%0,%1,%2,%3};"
        : "+f"(c[0]), "+f"(c[1]), "+f"(c[2]), "+f"(c[3])
        : "r"(a[0]), "r"(a[1]), "r"(a[2]), "r"(a[3]), "r"(b[0]), "r"(b[1]));
}
__device__ __forceinline__ void cp16(void* sptr, const void* gptr) {
    uint32_t s = (uint32_t)__cvta_generic_to_shared(sptr);
    asm volatile("cp.async.ca.shared.global [%0], [%1], 16;" :: "r"(s), "l"(gptr));
}
__device__ __forceinline__ void cp_commit() {
    asm volatile("cp.async.commit_group;");
}
template<int N> __device__ __forceinline__ void cp_wait() {
    asm volatile("cp.async.wait_group %0;" :: "n"(N));
}

// ------------------- block reductions -------------------
__device__ __forceinline__ float block_reduce_sum(float v) {
    __shared__ float sm[8];
    __shared__ float res;
    #pragma unroll
    for (int o = 16; o; o >>= 1) v += __shfl_xor_sync(0xffffffffu, v, o);
    if ((threadIdx.x & 31) == 0) sm[threadIdx.x >> 5] = v;
    __syncthreads();
    if (threadIdx.x < 32) {
        float t = (threadIdx.x < 8) ? sm[threadIdx.x] : 0.f;
        #pragma unroll
        for (int o = 4; o; o >>= 1) t += __shfl_xor_sync(0xffffffffu, t, o);
        if (threadIdx.x == 0) res = t;
    }
    __syncthreads();
    return res;
}

// ------------------- weight prep -------------------
__global__ void repack_qkv_kernel(const float* __restrict__ Wq,
                                  const float* __restrict__ Wk,
                                  const float* __restrict__ Wv,
                                  float* __restrict__ out) {
    int idx = blockIdx.x * blockDim.x + threadIdx.x;
    if (idx >= C_ * S3_) return;
    int c = idx / S3_, n = idx % S3_;
    const float* W = (n < C_) ? Wq : ((n < 2*C_) ? Wk : Wv);
    int nn = n % C_;
    out[idx] = to_tf32(W[((size_t)(nn / DH_) * C_ + c) * DH_ + (nn % DH_)]);
}

__global__ void round_copy_kernel(const float* __restrict__ in, float* __restrict__ out, int n4) {
    int i = blockIdx.x * blockDim.x + threadIdx.x;
    if (i >= n4) return;
    float4 f = reinterpret_cast<const float4*>(in)[i];
    f.x = to_tf32(f.x); f.y = to_tf32(f.y); f.z = to_tf32(f.z); f.w = to_tf32(f.w);
    reinterpret_cast<float4*>(out)[i] = f;
}

// ------------------- layernorm (output rounded to tf32) -------------------
__global__ void __launch_bounds__(256) ln_kernel(const float* __restrict__ x,
                                                 const float* __restrict__ g,
                                                 const float* __restrict__ b,
                                                 float* __restrict__ out) {
    size_t row = blockIdx.x;
    const float* xr = x + row * C_;
    float v[4]; float s = 0.f;
    #pragma unroll
    for (int i = 0; i < 4; i++) { v[i] = xr[threadIdx.x + i*256]; s += v[i]; }
    float mu = block_reduce_sum(s) * (1.f / C_);
    float s2 = 0.f;
    #pragma unroll
    for (int i = 0; i < 4; i++) { float d = v[i] - mu; s2 += d * d; }
    float rstd = rsqrtf(block_reduce_sum(s2) * (1.f / C_) + 1e-5f);
    float* orow = out + row * C_;
    #pragma unroll
    for (int i = 0; i < 4; i++) {
        int j = threadIdx.x + i*256;
        orow[j] = to_tf32((v[i] - mu) * rstd * g[j] + b[j]);
    }
}

// ------------------- fused flash attention (cp.async staged) -------------------
// grid (T/128, B*H), 256 threads = 8 warps; warp w owns q-rows [16w,16w+16).
// Q [128][68], K [128][68], V row-major [128][72].
__global__ void __launch_bounds__(256, 2) flash_kernel(const float* __restrict__ qkv,
                                                       float* __restrict__ o) {
    extern __shared__ float sm[];
    float* Qs = sm;                  // [128][68]
    float* Ks = Qs + 128*68;         // [128][68]
    float* Vs = Ks + 128*68;         // [128][72]  row-major [key][d]

    int bh = blockIdx.y, bb = bh >> 4, hh = bh & 15;
    int q0 = blockIdx.x * 128;
    const float* qb = qkv + (size_t)(bb*T_ + q0)*S3_ + hh*DH_;
    const float* kb = qkv + (size_t)bb*T_*S3_ + C_   + hh*DH_;
    const float* vb = qkv + (size_t)bb*T_*S3_ + 2*C_ + hh*DH_;

    int tid = threadIdx.x, wid = tid >> 5, lane = tid & 31;
    int g = lane >> 2, tq = lane & 3;
    int wm0 = wid * 16;

    // stage Q once (raw tf32; scale applied to S later)
    #pragma unroll
    for (int c = tid; c < 2048; c += 256) {
        int m = c >> 4, d4 = (c & 15) << 2;
        cp16(&Qs[m*68 + d4], qb + (size_t)m*S3_ + d4);
    }
    cp_commit();

    float mrow[2] = {-1e30f, -1e30f};
    float lrow[2] = {0.f, 0.f};
    float acc_o[8][4];
    #pragma unroll
    for (int dt = 0; dt < 8; dt++)
        #pragma unroll
        for (int r = 0; r < 4; r++) acc_o[dt][r] = 0.f;

    for (int n0 = 0; n0 < T_; n0 += 128) {
        __syncthreads();   // readers of previous K/V done
        #pragma unroll
        for (int c = tid; c < 2048; c += 256) {
            int n = c >> 4, d4 = (c & 15) << 2;
            cp16(&Ks[n*68 + d4], kb + (size_t)(n0+n)*S3_ + d4);
        }
        #pragma unroll
        for (int c = tid; c < 2048; c += 256) {
            int n = c >> 4, d4 = (c & 15) << 2;
            cp16(&Vs[n*72 + d4], vb + (size_t)(n0+n)*S3_ + d4);
        }
        cp_commit();
        cp_wait<0>();
        __syncthreads();

        // ---- S = Q K^T ----
        float s[16][4];
        #pragma unroll
        for (int nt = 0; nt < 16; nt++) { s[nt][0]=0.f; s[nt][1]=0.f; s[nt][2]=0.f; s[nt][3]=0.f; }
        #pragma unroll
        for (int ks = 0; ks < 8; ks++) {
            int kk = ks * 8;
            uint32_t a[4];
            a[0] = __float_as_uint(Qs[(wm0+g  )*68 + kk + tq    ]);
            a[1] = __float_as_uint(Qs[(wm0+g+8)*68 + kk + tq    ]);
            a[2] = __float_as_uint(Qs[(wm0+g  )*68 + kk + tq + 4]);
            a[3] = __float_as_uint(Qs[(wm0+g+8)*68 + kk + tq + 4]);
            #pragma unroll
            for (int nt = 0; nt < 16; nt++) {
                uint32_t b[2];
                b[0] = __float_as_uint(Ks[(nt*8+g)*68 + kk + tq    ]);
                b[1] = __float_as_uint(Ks[(nt*8+g)*68 + kk + tq + 4]);
                mma_tf32(s[nt], a, b);
            }
        }
        // fold in C^-0.5 = 1/32
        #pragma unroll
        for (int nt = 0; nt < 16; nt++) {
            s[nt][0] *= 0.03125f; s[nt][1] *= 0.03125f;
            s[nt][2] *= 0.03125f; s[nt][3] *= 0.03125f;
        }

        // ---- online softmax ----
        float mx0 = mrow[0], mx1 = mrow[1];
        #pragma unroll
        for (int nt = 0; nt < 16; nt++) {
            mx0 = fmaxf(mx0, fmaxf(s[nt][0], s[nt][1]));
            mx1 = fmaxf(mx1, fmaxf(s[nt][2], s[nt][3]));
        }
        mx0 = fmaxf(mx0, __shfl_xor_sync(0xffffffffu, mx0, 1));
        mx0 = fmaxf(mx0, __shfl_xor_sync(0xffffffffu, mx0, 2));
        mx1 = fmaxf(mx1, __shfl_xor_sync(0xffffffffu, mx1, 1));
        mx1 = fmaxf(mx1, __shfl_xor_sync(0xffffffffu, mx1, 2));
        float cf0 = exp2f((mrow[0]-mx0)*LOG2E);
        float cf1 = exp2f((mrow[1]-mx1)*LOG2E);
        mrow[0] = mx0; mrow[1] = mx1;
        #pragma unroll
        for (int dt = 0; dt < 8; dt++) {
            acc_o[dt][0] *= cf0; acc_o[dt][1] *= cf0;
            acc_o[dt][2] *= cf1; acc_o[dt][3] *= cf1;
        }

        // ---- P = exp(S - mx); O += P V  (P via quad shuffles, V row-major) ----
        float sum0 = 0.f, sum1 = 0.f;
        int src0 = (lane & ~3) | (tq >> 1);
        int src1 = src0 + 2;
        bool odd = (tq & 1);
        #pragma unroll
        for (int ks = 0; ks < 16; ks++) {
            float p0 = exp2f((s[ks][0]-mx0)*LOG2E);
            float p1 = exp2f((s[ks][1]-mx0)*LOG2E);
            float p2 = exp2f((s[ks][2]-mx1)*LOG2E);
            float p3 = exp2f((s[ks][3]-mx1)*LOG2E);
            sum0 += p0 + p1; sum1 += p2 + p3;
            uint32_t u0 = tf32u(p0), u1 = tf32u(p1), u2 = tf32u(p2), u3 = tf32u(p3);
            uint32_t w00 = __shfl_sync(0xffffffffu, u0, src0);
            uint32_t w01 = __shfl_sync(0xffffffffu, u1, src0);
            uint32_t w10 = __shfl_sync(0xffffffffu, u0, src1);
            uint32_t w11 = __shfl_sync(0xffffffffu, u1, src1);
            uint32_t x00 = __shfl_sync(0xffffffffu, u2, src0);
            uint32_t x01 = __shfl_sync(0xffffffffu, u3, src0);
            uint32_t x10 = __shfl_sync(0xffffffffu, u2, src1);
            uint32_t x11 = __shfl_sync(0xffffffffu, u3, src1);
            uint32_t a[4];
            a[0] = odd ? w01 : w00;
            a[2] = odd ? w11 : w10;
            a[1] = odd ? x01 : x00;
            a[3] = odd ? x11 : x10;
            int kk = ks * 8;
            #pragma unroll
            for (int dt = 0; dt < 8; dt++) {
                uint32_t b[2];
                b[0] = __float_as_uint(Vs[(kk + tq    )*72 + dt*8 + g]);
                b[1] = __float_as_uint(Vs[(kk + tq + 4)*72 + dt*8 + g]);
                mma_tf32(acc_o[dt], a, b);
            }
        }
        sum0 += __shfl_xor_sync(0xffffffffu, sum0, 1);
        sum0 += __shfl_xor_sync(0xffffffffu, sum0, 2);
        sum1 += __shfl_xor_sync(0xffffffffu, sum1, 1);
        sum1 += __shfl_xor_sync(0xffffffffu, sum1, 2);
        lrow[0] = lrow[0]*cf0 + sum0;
        lrow[1] = lrow[1]*cf1 + sum1;
    }

    float inv0 = 1.f / lrow[0], inv1 = 1.f / lrow[1];
    size_t r0 = (size_t)(bb*T_ + q0 + wm0 + g) * C_ + hh*DH_;
    size_t r1 = r0 + (size_t)8 * C_;
    #pragma unroll
    for (int dt = 0; dt < 8; dt++) {
        int col = dt*8 + 2*tq;
        o[r0 + col    ] = to_tf32(acc_o[dt][0] * inv0);
        o[r0 + col + 1] = to_tf32(acc_o[dt][1] * inv0);
        o[r1 + col    ] = to_tf32(acc_o[dt][2] * inv1);
        o[r1 + col + 1] = to_tf32(acc_o[dt][3] * inv1);
    }
}

// ------------------- tf32 GEMM: 3-stage cp.async pipeline -----------------------
// A (M x K) row-major, B (K x N) row-major, both pre-rounded to tf32.
// BM=BN=128, BK=16; 8 warps 4x2; warp tile 32x64; m16n8k8.
__global__ void __launch_bounds__(256, 2)
mma_gemm(const float* __restrict__ A, int lda,
         const float* __restrict__ B, int ldb,
         float* __restrict__ C, int ldc,
         int K,
         const float* __restrict__ bias,
         const float* __restrict__ resid, int relu, int round_out) {
    constexpr int AST = 20;    // A smem row stride
    constexpr int BST = 136;   // B smem row stride (136 % 32 == 8 -> conflict-free frags)
    constexpr int ASZ = 128*AST;   // 2560
    constexpr int BSZ = 16*BST;    // 2176
    extern __shared__ float smem[];
    float* As = smem;              // [3][ASZ]
    float* Bs = smem + 3*ASZ;      // [3][BSZ]

    int tid  = threadIdx.x;
    int wid  = tid >> 5;
    int lane = tid & 31;
    int g    = lane >> 2;
    int tq   = lane & 3;
    int wm0  = (wid & 3) * 32;
    int wn0  = (wid >> 2) * 64;
    int row0 = blockIdx.y * 128;
    int col0 = blockIdx.x * 128;

    auto stage = [&](int buf, int k0) {
        float* Ab = As + buf*ASZ;
        float* Bb = Bs + buf*BSZ;
        #pragma unroll
        for (int c = tid; c < 512; c += 256) {          // A: 128 rows x 16 k
            int m = c >> 2, k4 = (c & 3) << 2;
            cp16(&Ab[m*AST + k4], &A[(size_t)(row0 + m)*lda + k0 + k4]);
        }
        #pragma unroll
        for (int c = tid; c < 512; c += 256) {          // B: 16 k-rows x 128 n
            int kk = c >> 5, n4 = (c & 31) << 2;
            cp16(&Bb[kk*BST + n4], &B[(size_t)(k0 + kk)*ldb + col0 + n4]);
        }
    };

    float acc[2][8][4];
    #pragma unroll
    for (int i = 0; i < 2; i++)
        #pragma unroll
        for (int j = 0; j < 8; j++)
            #pragma unroll
            for (int r = 0; r < 4; r++) acc[i][j][r] = 0.f;

    stage(0, 0);  cp_commit();
    stage(1, 16); cp_commit();

    int NT = K >> 4;
    int buf = 0;
    for (int kt = 0; kt < NT; kt++) {
        cp_wait<1>();          // stage kt resident
        __syncthreads();       // visible to all; prev readers of reused buffer done
        if (kt + 2 < NT) stage((kt + 2) % 3, (kt + 2) << 4);
        cp_commit();           // possibly empty group: keeps pending-count invariant

        const float* Ab = As + buf*ASZ;
        const float* Bb = Bs + buf*BSZ;
        #pragma unroll
        for (int ks = 0; ks < 2; ks++) {
            int kb = ks * 8;
            uint32_t a[2][4], b[8][2];
            #pragma unroll
            for (int mt = 0; mt < 2; mt++) {
                int mr = wm0 + mt*16;
                a[mt][0] = __float_as_uint(Ab[(mr + g    )*AST + kb + tq    ]);
                a[mt][1] = __float_as_uint(Ab[(mr + g + 8)*AST + kb + tq    ]);
                a[mt][2] = __float_as_uint(Ab[(mr + g    )*AST + kb + tq + 4]);
                a[mt][3] = __float_as_uint(Ab[(mr + g + 8)*AST + kb + tq + 4]);
            }
            #pragma unroll
            for (int nt = 0; nt < 8; nt++) {
                int nc = wn0 + nt*8 + g;
                b[nt][0] = __float_as_uint(Bb[(kb + tq    )*BST + nc]);
                b[nt][1] = __float_as_uint(Bb[(kb + tq + 4)*BST + nc]);
            }
            #pragma unroll
            for (int mt = 0; mt < 2; mt++)
                #pragma unroll
                for (int nt = 0; nt < 8; nt++)
                    mma_tf32(acc[mt][nt], a[mt], b[nt]);
        }
        buf = (buf + 1) % 3;
    }

    // ---- epilogue (float2 stores) ----
    #pragma unroll
    for (int mt = 0; mt < 2; mt++) {
        int m0 = row0 + wm0 + mt*16 + g;
        #pragma unroll
        for (int nt = 0; nt < 8; nt++) {
            int n = col0 + wn0 + nt*8 + 2*tq;
            float bx = 0.f, by = 0.f;
            if (bias) { bx = bias[n]; by = bias[n+1]; }
            #pragma unroll
            for (int half = 0; half < 2; half++) {
                int m = m0 + half*8;
                float vx = acc[mt][nt][half*2+0] + bx;
                float vy = acc[mt][nt][half*2+1] + by;
                size_t ci = (size_t)m * ldc + n;
                if (resid) {
                    float2 rr = *reinterpret_cast<const float2*>(&resid[ci]);
                    vx += rr.x; vy += rr.y;
                }
                if (relu) { vx = fmaxf(vx, 0.f); vy = fmaxf(vy, 0.f); }
                if (round_out) { vx = to_tf32(vx); vy = to_tf32(vy); }
                float2 vv = make_float2(vx, vy);
                *reinterpret_cast<float2*>(&C[ci]) = vv;
            }
        }
    }
}

// ------------------- launcher ---------------------------------------------------
extern "C" void kernel_launch(void* const* d_in, const int* in_sizes, int n_in,
                              void* d_out, int out_size) {
    const float* x   = (const float*)d_in[0];
    const float* Wq  = (const float*)d_in[1];
    const float* Wk  = (const float*)d_in[2];
    const float* Wv  = (const float*)d_in[3];
    const float* Wo  = (const float*)d_in[4];
    const float* bo  = (const float*)d_in[5];
    const float* W1  = (const float*)d_in[6];
    const float* b1  = (const float*)d_in[7];
    const float* W2  = (const float*)d_in[8];
    const float* b2  = (const float*)d_in[9];
    const float* g1  = (const float*)d_in[10];
    const float* be1 = (const float*)d_in[11];
    const float* g2  = (const float*)d_in[12];
    const float* be2 = (const float*)d_in[13];
    float* out = (float*)d_out;

    float *h, *qkv, *o, *h2, *ff, *wqkv, *wor, *w1r, *w2r;
    cudaGetSymbolAddress((void**)&h,    g_h);
    cudaGetSymbolAddress((void**)&qkv,  g_qkv);
    cudaGetSymbolAddress((void**)&o,    g_o);
    cudaGetSymbolAddress((void**)&h2,   g_h2);
    cudaGetSymbolAddress((void**)&ff,   g_ff);
    cudaGetSymbolAddress((void**)&wqkv, g_Wqkv);
    cudaGetSymbolAddress((void**)&wor,  g_Wor);
    cudaGetSymbolAddress((void**)&w1r,  g_W1r);
    cudaGetSymbolAddress((void**)&w2r,  g_W2r);

    const int FLASH_SMEM = (128*68 + 128*68 + 128*72) * 4;          // 106496
    const int GEMM_SMEM  = (3*128*20 + 3*16*136) * 4;               // 56832
    static int smem_set = 0;
    if (!smem_set) {
        cudaFuncSetAttribute(flash_kernel,
                             cudaFuncAttributeMaxDynamicSharedMemorySize, FLASH_SMEM);
        cudaFuncSetAttribute(mma_gemm,
                             cudaFuncAttributeMaxDynamicSharedMemorySize, GEMM_SMEM);
        smem_set = 1;
    }

    // weight prep (tf32-rounded copies)
    repack_qkv_kernel<<<(C_*S3_ + 255)/256, 256>>>(Wq, Wk, Wv, wqkv);
    round_copy_kernel<<<(C_*C_/4 + 255)/256, 256>>>(Wo, wor, C_*C_/4);
    round_copy_kernel<<<(C_*FF_/4 + 255)/256, 256>>>(W1, w1r, C_*FF_/4);
    round_copy_kernel<<<(FF_*C_/4 + 255)/256, 256>>>(W2, w2r, FF_*C_/4);

    // LN1 (rounded output)
    ln_kernel<<<BT_, 256>>>(x, g1, be1, h);

    // qkv = h @ Wqkv  (rounded output)
    mma_gemm<<<dim3(S3_/128, BT_/128), 256, GEMM_SMEM>>>(
        h, C_, wqkv, S3_, qkv, S3_, C_, nullptr, nullptr, 0, 1);

    // fused attention -> o (rounded output)
    flash_kernel<<<dim3(T_/128, B_*H_), 256, FLASH_SMEM>>>(qkv, o);

    // x1 = x + o @ Wo + bo  -> d_out (exact fp32)
    mma_gemm<<<dim3(C_/128, BT_/128), 256, GEMM_SMEM>>>(
        o, C_, wor, C_, out, C_, C_, bo, x, 0, 0);

    // LN2 (rounded output)
    ln_kernel<<<BT_, 256>>>(out, g2, be2, h2);

    // ff = relu(h2 @ W1 + b1) (rounded output)
    mma_gemm<<<dim3(FF_/128, BT_/128), 256, GEMM_SMEM>>>(
        h2, C_, w1r, FF_, ff, FF_, C_, b1, nullptr, 1, 1);

    // out = x1 + ff @ W2 + b2
    mma_gemm<<<dim3(C_/128, BT_/128), 256, GEMM_SMEM>>>(
        ff, FF_, w2r, C_, out, C_, FF_, b2, out, 0, 0);
}

// round 6
// speedup vs baseline: 3.9221x; 1.0030x over previous
#include <cuda_runtime.h>
#include <math.h>
#include <stdint.h>

#define B_  2
#define T_  2048
#define C_  1024
#define H_  16
#define DH_ 64
#define BT_ (B_*T_)
#define FF_ (4*C_)
#define S3_ (3*C_)
#define LOG2E 1.4426950408889634f

// ------------------- device scratch (no allocations allowed) -------------------
__device__ float g_h   [BT_*C_];
__device__ float g_qkv [(size_t)BT_*S3_];
__device__ float g_o   [BT_*C_];
__device__ float g_h2  [BT_*C_];
__device__ float g_ff  [(size_t)BT_*FF_];
__device__ float g_Wqkv[(size_t)C_*S3_];
__device__ float g_Wor [(size_t)C_*C_];
__device__ float g_W1r [(size_t)C_*FF_];
__device__ float g_W2r [(size_t)FF_*C_];

// ------------------- tf32 / async helpers -------------------
__device__ __forceinline__ float to_tf32(float x) {
    uint32_t u;
    asm("cvt.rna.tf32.f32 %0, %1;" : "=r"(u) : "f"(x));
    return __uint_as_float(u);
}
__device__ __forceinline__ uint32_t tf32u(float x) {
    uint32_t u;
    asm("cvt.rna.tf32.f32 %0, %1;" : "=r"(u) : "f"(x));
    return u;
}
__device__ __forceinline__ void mma_tf32(float* c, const uint32_t* a, const uint32_t* b) {
    asm volatile(
        "mma.sync.aligned.m16n8k8.row.col.f32.tf32.tf32.f32 "
        "{%0,%1,%2,%3}, {%4,%5,%6,%7}, {%8,%9}, {%0,%1,%2,%3};"
        : "+f"(c[0]), "+f"(c[1]), "+f"(c[2]), "+f"(c[3])
        : "r"(a[0]), "r"(a[1]), "r"(a[2]), "r"(a[3]), "r"(b[0]), "r"(b[1]));
}
__device__ __forceinline__ void cp16(void* sptr, const void* gptr) {
    uint32_t s = (uint32_t)__cvta_generic_to_shared(sptr);
    asm volatile("cp.async.ca.shared.global [%0], [%1], 16;" :: "r"(s), "l"(gptr));
}
__device__ __forceinline__ void cp_commit() {
    asm volatile("cp.async.commit_group;");
}
template<int N> __device__ __forceinline__ void cp_wait() {
    asm volatile("cp.async.wait_group %0;" :: "n"(N));
}

// ------------------- block reductions -------------------
__device__ __forceinline__ float block_reduce_sum(float v) {
    __shared__ float sm[8];
    __shared__ float res;
    #pragma unroll
    for (int o = 16; o; o >>= 1) v += __shfl_xor_sync(0xffffffffu, v, o);
    if ((threadIdx.x & 31) == 0) sm[threadIdx.x >> 5] = v;
    __syncthreads();
    if (threadIdx.x < 32) {
        float t = (threadIdx.x < 8) ? sm[threadIdx.x] : 0.f;
        #pragma unroll
        for (int o = 4; o; o >>= 1) t += __shfl_xor_sync(0xffffffffu, t, o);
        if (threadIdx.x == 0) res = t;
    }
    __syncthreads();
    return res;
}

// ------------------- weight prep -------------------
__global__ void repack_qkv_kernel(const float* __restrict__ Wq,
                                  const float* __restrict__ Wk,
                                  const float* __restrict__ Wv,
                                  float* __restrict__ out) {
    int idx = blockIdx.x * blockDim.x + threadIdx.x;
    if (idx >= C_ * S3_) return;
    int c = idx / S3_, n = idx % S3_;
    const float* W = (n < C_) ? Wq : ((n < 2*C_) ? Wk : Wv);
    int nn = n % C_;
    out[idx] = to_tf32(W[((size_t)(nn / DH_) * C_ + c) * DH_ + (nn % DH_)]);
}

__global__ void round_copy_kernel(const float* __restrict__ in, float* __restrict__ out, int n4) {
    int i = blockIdx.x * blockDim.x + threadIdx.x;
    if (i >= n4) return;
    float4 f = reinterpret_cast<const float4*>(in)[i];
    f.x = to_tf32(f.x); f.y = to_tf32(f.y); f.z = to_tf32(f.z); f.w = to_tf32(f.w);
    reinterpret_cast<float4*>(out)[i] = f;
}

// ------------------- layernorm (output rounded to tf32) -------------------
__global__ void __launch_bounds__(256) ln_kernel(const float* __restrict__ x,
                                                 const float* __restrict__ g,
                                                 const float* __restrict__ b,
                                                 float* __restrict__ out) {
    size_t row = blockIdx.x;
    const float* xr = x + row * C_;
    float v[4]; float s = 0.f;
    #pragma unroll
    for (int i = 0; i < 4; i++) { v[i] = xr[threadIdx.x + i*256]; s += v[i]; }
    float mu = block_reduce_sum(s) * (1.f / C_);
    float s2 = 0.f;
    #pragma unroll
    for (int i = 0; i < 4; i++) { float d = v[i] - mu; s2 += d * d; }
    float rstd = rsqrtf(block_reduce_sum(s2) * (1.f / C_) + 1e-5f);
    float* orow = out + row * C_;
    #pragma unroll
    for (int i = 0; i < 4; i++) {
        int j = threadIdx.x + i*256;
        orow[j] = to_tf32((v[i] - mu) * rstd * g[j] + b[j]);
    }
}

// ------------------- fused flash attention (cp.async staged) -------------------
// grid (T/128, B*H), 256 threads = 8 warps; warp w owns q-rows [16w,16w+16).
// Q [128][68], K [128][68], V row-major [128][72].
__global__ void __launch_bounds__(256, 2) flash_kernel(const float* __restrict__ qkv,
                                                       float* __restrict__ o) {
    extern __shared__ float sm[];
    float* Qs = sm;                  // [128][68]
    float* Ks = Qs + 128*68;         // [128][68]
    float* Vs = Ks + 128*68;         // [128][72]  row-major [key][d]

    int bh = blockIdx.y, bb = bh >> 4, hh = bh & 15;
    int q0 = blockIdx.x * 128;
    const float* qb = qkv + (size_t)(bb*T_ + q0)*S3_ + hh*DH_;
    const float* kb = qkv + (size_t)bb*T_*S3_ + C_   + hh*DH_;
    const float* vb = qkv + (size_t)bb*T_*S3_ + 2*C_ + hh*DH_;

    int tid = threadIdx.x, wid = tid >> 5, lane = tid & 31;
    int g = lane >> 2, tq = lane & 3;
    int wm0 = wid * 16;

    // stage Q once (raw tf32; scale applied to S later)
    #pragma unroll
    for (int c = tid; c < 2048; c += 256) {
        int m = c >> 4, d4 = (c & 15) << 2;
        cp16(&Qs[m*68 + d4], qb + (size_t)m*S3_ + d4);
    }
    cp_commit();

    float mrow[2] = {-1e30f, -1e30f};
    float lrow[2] = {0.f, 0.f};
    float acc_o[8][4];
    #pragma unroll
    for (int dt = 0; dt < 8; dt++)
        #pragma unroll
        for (int r = 0; r < 4; r++) acc_o[dt][r] = 0.f;

    for (int n0 = 0; n0 < T_; n0 += 128) {
        __syncthreads();   // readers of previous K/V done
        #pragma unroll
        for (int c = tid; c < 2048; c += 256) {
            int n = c >> 4, d4 = (c & 15) << 2;
            cp16(&Ks[n*68 + d4], kb + (size_t)(n0+n)*S3_ + d4);
        }
        #pragma unroll
        for (int c = tid; c < 2048; c += 256) {
            int n = c >> 4, d4 = (c & 15) << 2;
            cp16(&Vs[n*72 + d4], vb + (size_t)(n0+n)*S3_ + d4);
        }
        cp_commit();
        cp_wait<0>();
        __syncthreads();

        // ---- S = Q K^T ----
        float s[16][4];
        #pragma unroll
        for (int nt = 0; nt < 16; nt++) { s[nt][0]=0.f; s[nt][1]=0.f; s[nt][2]=0.f; s[nt][3]=0.f; }
        #pragma unroll
        for (int ks = 0; ks < 8; ks++) {
            int kk = ks * 8;
            uint32_t a[4];
            a[0] = __float_as_uint(Qs[(wm0+g  )*68 + kk + tq    ]);
            a[1] = __float_as_uint(Qs[(wm0+g+8)*68 + kk + tq    ]);
            a[2] = __float_as_uint(Qs[(wm0+g  )*68 + kk + tq + 4]);
            a[3] = __float_as_uint(Qs[(wm0+g+8)*68 + kk + tq + 4]);
            #pragma unroll
            for (int nt = 0; nt < 16; nt++) {
                uint32_t b[2];
                b[0] = __float_as_uint(Ks[(nt*8+g)*68 + kk + tq    ]);
                b[1] = __float_as_uint(Ks[(nt*8+g)*68 + kk + tq + 4]);
                mma_tf32(s[nt], a, b);
            }
        }
        // fold in C^-0.5 = 1/32
        #pragma unroll
        for (int nt = 0; nt < 16; nt++) {
            s[nt][0] *= 0.03125f; s[nt][1] *= 0.03125f;
            s[nt][2] *= 0.03125f; s[nt][3] *= 0.03125f;
        }

        // ---- online softmax ----
        float mx0 = mrow[0], mx1 = mrow[1];
        #pragma unroll
        for (int nt = 0; nt < 16; nt++) {
            mx0 = fmaxf(mx0, fmaxf(s[nt][0], s[nt][1]));
            mx1 = fmaxf(mx1, fmaxf(s[nt][2], s[nt][3]));
        }
        mx0 = fmaxf(mx0, __shfl_xor_sync(0xffffffffu, mx0, 1));
        mx0 = fmaxf(mx0, __shfl_xor_sync(0xffffffffu, mx0, 2));
        mx1 = fmaxf(mx1, __shfl_xor_sync(0xffffffffu, mx1, 1));
        mx1 = fmaxf(mx1, __shfl_xor_sync(0xffffffffu, mx1, 2));
        float cf0 = exp2f((mrow[0]-mx0)*LOG2E);
        float cf1 = exp2f((mrow[1]-mx1)*LOG2E);
        mrow[0] = mx0; mrow[1] = mx1;
        #pragma unroll
        for (int dt = 0; dt < 8; dt++) {
            acc_o[dt][0] *= cf0; acc_o[dt][1] *= cf0;
            acc_o[dt][2] *= cf1; acc_o[dt][3] *= cf1;
        }

        // ---- P = exp(S - mx); O += P V  (P via quad shuffles, V row-major) ----
        float sum0 = 0.f, sum1 = 0.f;
        int src0 = (lane & ~3) | (tq >> 1);
        int src1 = src0 + 2;
        bool odd = (tq & 1);
        #pragma unroll
        for (int ks = 0; ks < 16; ks++) {
            float p0 = exp2f((s[ks][0]-mx0)*LOG2E);
            float p1 = exp2f((s[ks][1]-mx0)*LOG2E);
            float p2 = exp2f((s[ks][2]-mx1)*LOG2E);
            float p3 = exp2f((s[ks][3]-mx1)*LOG2E);
            sum0 += p0 + p1; sum1 += p2 + p3;
            uint32_t u0 = tf32u(p0), u1 = tf32u(p1), u2 = tf32u(p2), u3 = tf32u(p3);
            uint32_t w00 = __shfl_sync(0xffffffffu, u0, src0);
            uint32_t w01 = __shfl_sync(0xffffffffu, u1, src0);
            uint32_t w10 = __shfl_sync(0xffffffffu, u0, src1);
            uint32_t w11 = __shfl_sync(0xffffffffu, u1, src1);
            uint32_t x00 = __shfl_sync(0xffffffffu, u2, src0);
            uint32_t x01 = __shfl_sync(0xffffffffu, u3, src0);
            uint32_t x10 = __shfl_sync(0xffffffffu, u2, src1);
            uint32_t x11 = __shfl_sync(0xffffffffu, u3, src1);
            uint32_t a[4];
            a[0] = odd ? w01 : w00;
            a[2] = odd ? w11 : w10;
            a[1] = odd ? x01 : x00;
            a[3] = odd ? x11 : x10;
            int kk = ks * 8;
            #pragma unroll
            for (int dt = 0; dt < 8; dt++) {
                uint32_t b[2];
                b[0] = __float_as_uint(Vs[(kk + tq    )*72 + dt*8 + g]);
                b[1] = __float_as_uint(Vs[(kk + tq + 4)*72 + dt*8 + g]);
                mma_tf32(acc_o[dt], a, b);
            }
        }
        sum0 += __shfl_xor_sync(0xffffffffu, sum0, 1);
        sum0 += __shfl_xor_sync(0xffffffffu, sum0, 2);
        sum1 += __shfl_xor_sync(0xffffffffu, sum1, 1);
        sum1 += __shfl_xor_sync(0xffffffffu, sum1, 2);
        lrow[0] = lrow[0]*cf0 + sum0;
        lrow[1] = lrow[1]*cf1 + sum1;
    }

    float inv0 = 1.f / lrow[0], inv1 = 1.f / lrow[1];
    size_t r0 = (size_t)(bb*T_ + q0 + wm0 + g) * C_ + hh*DH_;
    size_t r1 = r0 + (size_t)8 * C_;
    #pragma unroll
    for (int dt = 0; dt < 8; dt++) {
        int col = dt*8 + 2*tq;
        o[r0 + col    ] = to_tf32(acc_o[dt][0] * inv0);
        o[r0 + col + 1] = to_tf32(acc_o[dt][1] * inv0);
        o[r1 + col    ] = to_tf32(acc_o[dt][2] * inv1);
        o[r1 + col + 1] = to_tf32(acc_o[dt][3] * inv1);
    }
}

// ------------------- tf32 GEMM: 3-stage cp.async pipeline -----------------------
// A (M x K) row-major, B (K x N) row-major, both pre-rounded to tf32.
// BM=BN=128, BK=16; 8 warps 4x2; warp tile 32x64; m16n8k8.
__global__ void __launch_bounds__(256, 2)
mma_gemm(const float* __restrict__ A, int lda,
         const float* __restrict__ B, int ldb,
         float* __restrict__ C, int ldc,
         int K,
         const float* __restrict__ bias,
         const float* __restrict__ resid, int relu, int round_out) {
    constexpr int AST = 20;    // A smem row stride
    constexpr int BST = 136;   // B smem row stride (136 % 32 == 8 -> conflict-free frags)
    constexpr int ASZ = 128*AST;   // 2560
    constexpr int BSZ = 16*BST;    // 2176
    extern __shared__ float smem[];
    float* As = smem;              // [3][ASZ]
    float* Bs = smem + 3*ASZ;      // [3][BSZ]

    int tid  = threadIdx.x;
    int wid  = tid >> 5;
    int lane = tid & 31;
    int g    = lane >> 2;
    int tq   = lane & 3;
    int wm0  = (wid & 3) * 32;
    int wn0  = (wid >> 2) * 64;
    int row0 = blockIdx.y * 128;
    int col0 = blockIdx.x * 128;

    auto stage = [&](int buf, int k0) {
        float* Ab = As + buf*ASZ;
        float* Bb = Bs + buf*BSZ;
        #pragma unroll
        for (int c = tid; c < 512; c += 256) {          // A: 128 rows x 16 k
            int m = c >> 2, k4 = (c & 3) << 2;
            cp16(&Ab[m*AST + k4], &A[(size_t)(row0 + m)*lda + k0 + k4]);
        }
        #pragma unroll
        for (int c = tid; c < 512; c += 256) {          // B: 16 k-rows x 128 n
            int kk = c >> 5, n4 = (c & 31) << 2;
            cp16(&Bb[kk*BST + n4], &B[(size_t)(k0 + kk)*ldb + col0 + n4]);
        }
    };

    float acc[2][8][4];
    #pragma unroll
    for (int i = 0; i < 2; i++)
        #pragma unroll
        for (int j = 0; j < 8; j++)
            #pragma unroll
            for (int r = 0; r < 4; r++) acc[i][j][r] = 0.f;

    stage(0, 0);  cp_commit();
    stage(1, 16); cp_commit();

    int NT = K >> 4;
    int buf = 0;
    for (int kt = 0; kt < NT; kt++) {
        cp_wait<1>();          // stage kt resident
        __syncthreads();       // visible to all; prev readers of reused buffer done
        if (kt + 2 < NT) stage((kt + 2) % 3, (kt + 2) << 4);
        cp_commit();           // possibly empty group: keeps pending-count invariant

        const float* Ab = As + buf*ASZ;
        const float* Bb = Bs + buf*BSZ;
        #pragma unroll
        for (int ks = 0; ks < 2; ks++) {
            int kb = ks * 8;
            uint32_t a[2][4], b[8][2];
            #pragma unroll
            for (int mt = 0; mt < 2; mt++) {
                int mr = wm0 + mt*16;
                a[mt][0] = __float_as_uint(Ab[(mr + g    )*AST + kb + tq    ]);
                a[mt][1] = __float_as_uint(Ab[(mr + g + 8)*AST + kb + tq    ]);
                a[mt][2] = __float_as_uint(Ab[(mr + g    )*AST + kb + tq + 4]);
                a[mt][3] = __float_as_uint(Ab[(mr + g + 8)*AST + kb + tq + 4]);
            }
            #pragma unroll
            for (int nt = 0; nt < 8; nt++) {
                int nc = wn0 + nt*8 + g;
                b[nt][0] = __float_as_uint(Bb[(kb + tq    )*BST + nc]);
                b[nt][1] = __float_as_uint(Bb[(kb + tq + 4)*BST + nc]);
            }
            #pragma unroll
            for (int mt = 0; mt < 2; mt++)
                #pragma unroll
                for (int nt = 0; nt < 8; nt++)
                    mma_tf32(acc[mt][nt], a[mt], b[nt]);
        }
        buf = (buf + 1) % 3;
    }

    // ---- epilogue (float2 stores) ----
    #pragma unroll
    for (int mt = 0; mt < 2; mt++) {
        int m0 = row0 + wm0 + mt*16 + g;
        #pragma unroll
        for (int nt = 0; nt < 8; nt++) {
            int n = col0 + wn0 + nt*8 + 2*tq;
            float bx = 0.f, by = 0.f;
            if (bias) { bx = bias[n]; by = bias[n+1]; }
            #pragma unroll
            for (int half = 0; half < 2; half++) {
                int m = m0 + half*8;
                float vx = acc[mt][nt][half*2+0] + bx;
                float vy = acc[mt][nt][half*2+1] + by;
                size_t ci = (size_t)m * ldc + n;
                if (resid) {
                    float2 rr = *reinterpret_cast<const float2*>(&resid[ci]);
                    vx += rr.x; vy += rr.y;
                }
                if (relu) { vx = fmaxf(vx, 0.f); vy = fmaxf(vy, 0.f); }
                if (round_out) { vx = to_tf32(vx); vy = to_tf32(vy); }
                float2 vv = make_float2(vx, vy);
                *reinterpret_cast<float2*>(&C[ci]) = vv;
            }
        }
    }
}

// ------------------- launcher ---------------------------------------------------
extern "C" void kernel_launch(void* const* d_in, const int* in_sizes, int n_in,
                              void* d_out, int out_size) {
    const float* x   = (const float*)d_in[0];
    const float* Wq  = (const float*)d_in[1];
    const float* Wk  = (const float*)d_in[2];
    const float* Wv  = (const float*)d_in[3];
    const float* Wo  = (const float*)d_in[4];
    const float* bo  = (const float*)d_in[5];
    const float* W1  = (const float*)d_in[6];
    const float* b1  = (const float*)d_in[7];
    const float* W2  = (const float*)d_in[8];
    const float* b2  = (const float*)d_in[9];
    const float* g1  = (const float*)d_in[10];
    const float* be1 = (const float*)d_in[11];
    const float* g2  = (const float*)d_in[12];
    const float* be2 = (const float*)d_in[13];
    float* out = (float*)d_out;

    float *h, *qkv, *o, *h2, *ff, *wqkv, *wor, *w1r, *w2r;
    cudaGetSymbolAddress((void**)&h,    g_h);
    cudaGetSymbolAddress((void**)&qkv,  g_qkv);
    cudaGetSymbolAddress((void**)&o,    g_o);
    cudaGetSymbolAddress((void**)&h2,   g_h2);
    cudaGetSymbolAddress((void**)&ff,   g_ff);
    cudaGetSymbolAddress((void**)&wqkv, g_Wqkv);
    cudaGetSymbolAddress((void**)&wor,  g_Wor);
    cudaGetSymbolAddress((void**)&w1r,  g_W1r);
    cudaGetSymbolAddress((void**)&w2r,  g_W2r);

    const int FLASH_SMEM = (128*68 + 128*68 + 128*72) * 4;          // 106496
    const int GEMM_SMEM  = (3*128*20 + 3*16*136) * 4;               // 56832
    static int smem_set = 0;
    if (!smem_set) {
        cudaFuncSetAttribute(flash_kernel,
                             cudaFuncAttributeMaxDynamicSharedMemorySize, FLASH_SMEM);
        cudaFuncSetAttribute(mma_gemm,
                             cudaFuncAttributeMaxDynamicSharedMemorySize, GEMM_SMEM);
        smem_set = 1;
    }

    // weight prep (tf32-rounded copies)
    repack_qkv_kernel<<<(C_*S3_ + 255)/256, 256>>>(Wq, Wk, Wv, wqkv);
    round_copy_kernel<<<(C_*C_/4 + 255)/256, 256>>>(Wo, wor, C_*C_/4);
    round_copy_kernel<<<(C_*FF_/4 + 255)/256, 256>>>(W1, w1r, C_*FF_/4);
    round_copy_kernel<<<(FF_*C_/4 + 255)/256, 256>>>(W2, w2r, FF_*C_/4);

    // LN1 (rounded output)
    ln_kernel<<<BT_, 256>>>(x, g1, be1, h);

    // qkv = h @ Wqkv  (rounded output)
    mma_gemm<<<dim3(S3_/128, BT_/128), 256, GEMM_SMEM>>>(
        h, C_, wqkv, S3_, qkv, S3_, C_, nullptr, nullptr, 0, 1);

    // fused attention -> o (rounded output)
    flash_kernel<<<dim3(T_/128, B_*H_), 256, FLASH_SMEM>>>(qkv, o);

    // x1 = x + o @ Wo + bo  -> d_out (exact fp32)
    mma_gemm<<<dim3(C_/128, BT_/128), 256, GEMM_SMEM>>>(
        o, C_, wor, C_, out, C_, C_, bo, x, 0, 0);

    // LN2 (rounded output)
    ln_kernel<<<BT_, 256>>>(out, g2, be2, h2);

    // ff = relu(h2 @ W1 + b1) (rounded output)
    mma_gemm<<<dim3(FF_/128, BT_/128), 256, GEMM_SMEM>>>(
        h2, C_, w1r, FF_, ff, FF_, C_, b1, nullptr, 1, 1);

    // out = x1 + ff @ W2 + b2
    mma_gemm<<<dim3(C_/128, BT_/128), 256, GEMM_SMEM>>>(
        ff, FF_, w2r, C_, out, C_, FF_, b2, out, 0, 0);
}

// round 8
// speedup vs baseline: 4.3236x; 1.1024x over previous
#include <cuda_runtime.h>
#include <math.h>
#include <stdint.h>

#define B_  2
#define T_  2048
#define C_  1024
#define H_  16
#define DH_ 64
#define BT_ (B_*T_)
#define FF_ (4*C_)
#define S3_ (3*C_)
#define LOG2E 1.4426950408889634f

// ------------------- device scratch -------------------
__device__ float g_h    [BT_*C_];
__device__ float g_qkv  [(size_t)BT_*S3_];
__device__ float g_o    [BT_*C_];
__device__ float g_h2   [BT_*C_];
__device__ float g_ff   [(size_t)BT_*FF_];
__device__ float g_WqkvT[(size_t)S3_*C_];   // [N=3C][K=C]
__device__ float g_WoT  [(size_t)C_*C_];    // [N=C][K=C]
__device__ float g_W1T  [(size_t)FF_*C_];   // [N=FF][K=C]
__device__ float g_W2T  [(size_t)C_*FF_];   // [N=C][K=FF]

// ------------------- helpers -------------------
__device__ __forceinline__ float to_tf32(float x) {
    uint32_t u; asm("cvt.rna.tf32.f32 %0, %1;" : "=r"(u) : "f"(x));
    return __uint_as_float(u);
}
__device__ __forceinline__ uint32_t tf32u(float x) {
    uint32_t u; asm("cvt.rna.tf32.f32 %0, %1;" : "=r"(u) : "f"(x));
    return u;
}
__device__ __forceinline__ void mma_tf32(float* c, const uint32_t* a, const uint32_t* b) {
    asm volatile(
        "mma.sync.aligned.m16n8k8.row.col.f32.tf32.tf32.f32 "
        "{%0,%1,%2,%3}, {%4,%5,%6,%7}, {%8,%9}, {%0,%1,%2,%3};"
        : "+f"(c[0]), "+f"(c[1]), "+f"(c[2]), "+f"(c[3])
        : "r"(a[0]), "r"(a[1]), "r"(a[2]), "r"(a[3]), "r"(b[0]), "r"(b[1]));
}
__device__ __forceinline__ void cp16(void* sptr, const void* gptr) {
    uint32_t s = (uint32_t)__cvta_generic_to_shared(sptr);
    asm volatile("cp.async.ca.shared.global [%0], [%1], 16;" :: "r"(s), "l"(gptr));
}
__device__ __forceinline__ void cp_commit() { asm volatile("cp.async.commit_group;"); }
template<int N> __device__ __forceinline__ void cp_wait() {
    asm volatile("cp.async.wait_group %0;" :: "n"(N));
}

__device__ __forceinline__ float block_reduce_sum(float v) {
    __shared__ float sm[8];
    __shared__ float res;
    #pragma unroll
    for (int o = 16; o; o >>= 1) v += __shfl_xor_sync(0xffffffffu, v, o);
    if ((threadIdx.x & 31) == 0) sm[threadIdx.x >> 5] = v;
    __syncthreads();
    if (threadIdx.x < 32) {
        float t = (threadIdx.x < 8) ? sm[threadIdx.x] : 0.f;
        #pragma unroll
        for (int o = 4; o; o >>= 1) t += __shfl_xor_sync(0xffffffffu, t, o);
        if (threadIdx.x == 0) res = t;
    }
    __syncthreads();
    return res;
}

// ------------------- weight transposes (to [N][K], tf32-rounded) ---------------
__global__ void qkv_transpose(const float* __restrict__ Wq, const float* __restrict__ Wk,
                              const float* __restrict__ Wv, float* __restrict__ out) {
    __shared__ float t[32][33];
    int k0 = blockIdx.y * 32, n0 = blockIdx.x * 32;
    int tx = threadIdx.x, ty = threadIdx.y;
    int n = n0 + tx;
    const float* W = (n < C_) ? Wq : ((n < 2*C_) ? Wk : Wv);
    int nn = n % C_;
    for (int i = ty; i < 32; i += 8)
        t[i][tx] = W[((size_t)(nn/DH_)*C_ + (k0+i))*DH_ + (nn%DH_)];
    __syncthreads();
    for (int i = ty; i < 32; i += 8)
        out[(size_t)(n0+i)*C_ + k0 + tx] = to_tf32(t[tx][i]);
}

__global__ void wt_transpose(const float* __restrict__ in, float* __restrict__ out,
                             int K, int N) {
    __shared__ float t[32][33];
    int k0 = blockIdx.y * 32, n0 = blockIdx.x * 32;
    int tx = threadIdx.x, ty = threadIdx.y;
    for (int i = ty; i < 32; i += 8)
        t[i][tx] = in[(size_t)(k0+i)*N + n0 + tx];
    __syncthreads();
    for (int i = ty; i < 32; i += 8)
        out[(size_t)(n0+i)*K + k0 + tx] = to_tf32(t[tx][i]);
}

// ------------------- layernorm (tf32-rounded output) -------------------
__global__ void __launch_bounds__(256) ln_kernel(const float* __restrict__ x,
                                                 const float* __restrict__ g,
                                                 const float* __restrict__ b,
                                                 float* __restrict__ out) {
    size_t row = blockIdx.x;
    const float* xr = x + row * C_;
    float v[4]; float s = 0.f;
    #pragma unroll
    for (int i = 0; i < 4; i++) { v[i] = xr[threadIdx.x + i*256]; s += v[i]; }
    float mu = block_reduce_sum(s) * (1.f / C_);
    float s2 = 0.f;
    #pragma unroll
    for (int i = 0; i < 4; i++) { float d = v[i] - mu; s2 += d * d; }
    float rstd = rsqrtf(block_reduce_sum(s2) * (1.f / C_) + 1e-5f);
    float* orow = out + row * C_;
    #pragma unroll
    for (int i = 0; i < 4; i++) {
        int j = threadIdx.x + i*256;
        orow[j] = to_tf32((v[i] - mu) * rstd * g[j] + b[j]);
    }
}

// ------------------- fused flash attention (identical to R4-passing) -----------
__global__ void __launch_bounds__(256, 2) flash_kernel(const float* __restrict__ qkv,
                                                       float* __restrict__ o) {
    extern __shared__ float sm[];
    float* Qs = sm;                  // [128][68]
    float* Ks = Qs + 128*68;         // [128][68]
    float* Vs = Ks + 128*68;         // [128][72]

    int bh = blockIdx.y, bb = bh >> 4, hh = bh & 15;
    int q0 = blockIdx.x * 128;
    const float* qb = qkv + (size_t)(bb*T_ + q0)*S3_ + hh*DH_;
    const float* kb = qkv + (size_t)bb*T_*S3_ + C_   + hh*DH_;
    const float* vb = qkv + (size_t)bb*T_*S3_ + 2*C_ + hh*DH_;

    int tid = threadIdx.x, wid = tid >> 5, lane = tid & 31;
    int g = lane >> 2, tq = lane & 3;
    int wm0 = wid * 16;

    #pragma unroll
    for (int c = tid; c < 2048; c += 256) {
        int m = c >> 4, d4 = (c & 15) << 2;
        cp16(&Qs[m*68 + d4], qb + (size_t)m*S3_ + d4);
    }
    cp_commit();

    float mrow[2] = {-1e30f, -1e30f};
    float lrow[2] = {0.f, 0.f};
    float acc_o[8][4];
    #pragma unroll
    for (int dt = 0; dt < 8; dt++)
        #pragma unroll
        for (int r = 0; r < 4; r++) acc_o[dt][r] = 0.f;

    for (int n0 = 0; n0 < T_; n0 += 128) {
        __syncthreads();
        #pragma unroll
        for (int c = tid; c < 2048; c += 256) {
            int n = c >> 4, d4 = (c & 15) << 2;
            cp16(&Ks[n*68 + d4], kb + (size_t)(n0+n)*S3_ + d4);
        }
        #pragma unroll
        for (int c = tid; c < 2048; c += 256) {
            int n = c >> 4, d4 = (c & 15) << 2;
            cp16(&Vs[n*72 + d4], vb + (size_t)(n0+n)*S3_ + d4);
        }
        cp_commit();
        cp_wait<0>();
        __syncthreads();

        float s[16][4];
        #pragma unroll
        for (int nt = 0; nt < 16; nt++) { s[nt][0]=0.f; s[nt][1]=0.f; s[nt][2]=0.f; s[nt][3]=0.f; }
        #pragma unroll
        for (int ks = 0; ks < 8; ks++) {
            int kk = ks * 8;
            uint32_t a[4];
            a[0] = __float_as_uint(Qs[(wm0+g  )*68 + kk + tq    ]);
            a[1] = __float_as_uint(Qs[(wm0+g+8)*68 + kk + tq    ]);
            a[2] = __float_as_uint(Qs[(wm0+g  )*68 + kk + tq + 4]);
            a[3] = __float_as_uint(Qs[(wm0+g+8)*68 + kk + tq + 4]);
            #pragma unroll
            for (int nt = 0; nt < 16; nt++) {
                uint32_t b[2];
                b[0] = __float_as_uint(Ks[(nt*8+g)*68 + kk + tq    ]);
                b[1] = __float_as_uint(Ks[(nt*8+g)*68 + kk + tq + 4]);
                mma_tf32(s[nt], a, b);
            }
        }
        #pragma unroll
        for (int nt = 0; nt < 16; nt++) {
            s[nt][0] *= 0.03125f; s[nt][1] *= 0.03125f;
            s[nt][2] *= 0.03125f; s[nt][3] *= 0.03125f;
        }

        float mx0 = mrow[0], mx1 = mrow[1];
        #pragma unroll
        for (int nt = 0; nt < 16; nt++) {
            mx0 = fmaxf(mx0, fmaxf(s[nt][0], s[nt][1]));
            mx1 = fmaxf(mx1, fmaxf(s[nt][2], s[nt][3]));
        }
        mx0 = fmaxf(mx0, __shfl_xor_sync(0xffffffffu, mx0, 1));
        mx0 = fmaxf(mx0, __shfl_xor_sync(0xffffffffu, mx0, 2));
        mx1 = fmaxf(mx1, __shfl_xor_sync(0xffffffffu, mx1, 1));
        mx1 = fmaxf(mx1, __shfl_xor_sync(0xffffffffu, mx1, 2));
        float cf0 = exp2f((mrow[0]-mx0)*LOG2E);
        float cf1 = exp2f((mrow[1]-mx1)*LOG2E);
        mrow[0] = mx0; mrow[1] = mx1;
        #pragma unroll
        for (int dt = 0; dt < 8; dt++) {
            acc_o[dt][0] *= cf0; acc_o[dt][1] *= cf0;
            acc_o[dt][2] *= cf1; acc_o[dt][3] *= cf1;
        }

        float sum0 = 0.f, sum1 = 0.f;
        int src0 = (lane & ~3) | (tq >> 1);
        int src1 = src0 + 2;
        bool odd = (tq & 1);
        #pragma unroll
        for (int ks = 0; ks < 16; ks++) {
            float p0 = exp2f((s[ks][0]-mx0)*LOG2E);
            float p1 = exp2f((s[ks][1]-mx0)*LOG2E);
            float p2 = exp2f((s[ks][2]-mx1)*LOG2E);
            float p3 = exp2f((s[ks][3]-mx1)*LOG2E);
            sum0 += p0 + p1; sum1 += p2 + p3;
            uint32_t u0 = tf32u(p0), u1 = tf32u(p1), u2 = tf32u(p2), u3 = tf32u(p3);
            uint32_t w00 = __shfl_sync(0xffffffffu, u0, src0);
            uint32_t w01 = __shfl_sync(0xffffffffu, u1, src0);
            uint32_t w10 = __shfl_sync(0xffffffffu, u0, src1);
            uint32_t w11 = __shfl_sync(0xffffffffu, u1, src1);
            uint32_t x00 = __shfl_sync(0xffffffffu, u2, src0);
            uint32_t x01 = __shfl_sync(0xffffffffu, u3, src0);
            uint32_t x10 = __shfl_sync(0xffffffffu, u2, src1);
            uint32_t x11 = __shfl_sync(0xffffffffu, u3, src1);
            uint32_t a[4];
            a[0] = odd ? w01 : w00;
            a[2] = odd ? w11 : w10;
            a[1] = odd ? x01 : x00;
            a[3] = odd ? x11 : x10;
            int kk = ks * 8;
            #pragma unroll
            for (int dt = 0; dt < 8; dt++) {
                uint32_t b[2];
                b[0] = __float_as_uint(Vs[(kk + tq    )*72 + dt*8 + g]);
                b[1] = __float_as_uint(Vs[(kk + tq + 4)*72 + dt*8 + g]);
                mma_tf32(acc_o[dt], a, b);
            }
        }
        sum0 += __shfl_xor_sync(0xffffffffu, sum0, 1);
        sum0 += __shfl_xor_sync(0xffffffffu, sum0, 2);
        sum1 += __shfl_xor_sync(0xffffffffu, sum1, 1);
        sum1 += __shfl_xor_sync(0xffffffffu, sum1, 2);
        lrow[0] = lrow[0]*cf0 + sum0;
        lrow[1] = lrow[1]*cf1 + sum1;
    }

    float inv0 = 1.f / lrow[0], inv1 = 1.f / lrow[1];
    size_t r0 = (size_t)(bb*T_ + q0 + wm0 + g) * C_ + hh*DH_;
    size_t r1 = r0 + (size_t)8 * C_;
    #pragma unroll
    for (int dt = 0; dt < 8; dt++) {
        int col = dt*8 + 2*tq;
        o[r0 + col    ] = to_tf32(acc_o[dt][0] * inv0);
        o[r0 + col + 1] = to_tf32(acc_o[dt][1] * inv0);
        o[r1 + col    ] = to_tf32(acc_o[dt][2] * inv1);
        o[r1 + col + 1] = to_tf32(acc_o[dt][3] * inv1);
    }
}

// ------------------- tf32 GEMM: 4 warps of 64x64, BK=32, 2-stage cp.async ------
// A [M][K] row-major tf32; W [N][K] row-major tf32 (transposed weights).
__global__ void __launch_bounds__(128)
mma_gemm(const float* __restrict__ A, int lda,
         const float* __restrict__ W, int K,
         float* __restrict__ C, int ldc,
         const float* __restrict__ bias,
         const float* __restrict__ resid, int relu, int round_out) {
    constexpr int ST = 36;          // row stride: (4g+tq)%32 distinct -> conflict-free
    constexpr int TS = 128*ST;      // one tile (A or B) in floats
    extern __shared__ float smem[];
    float* As = smem;               // [2][128][36]
    float* Bs = smem + 2*TS;        // [2][128][36]

    int tid = threadIdx.x, wid = tid >> 5, lane = tid & 31;
    int g = lane >> 2, tq = lane & 3;
    int wm0 = (wid & 1) * 64;       // 2x2 warp grid, 64x64 each
    int wn0 = (wid >> 1) * 64;
    int row0 = blockIdx.y * 128, col0 = blockIdx.x * 128;

    auto stage = [&](int b, int kt) {
        float* Ab = As + b*TS;
        float* Bb = Bs + b*TS;
        int k0 = kt << 5;
        #pragma unroll
        for (int c = tid; c < 1024; c += 128) {
            int m = c >> 3, ch = c & 7;
            cp16(&Ab[m*ST + ch*4], A + (size_t)(row0 + m)*lda + k0 + ch*4);
        }
        #pragma unroll
        for (int c = tid; c < 1024; c += 128) {
            int n = c >> 3, ch = c & 7;
            cp16(&Bb[n*ST + ch*4], W + (size_t)(col0 + n)*K + k0 + ch*4);
        }
    };

    float acc[4][8][4];
    #pragma unroll
    for (int i = 0; i < 4; i++)
        #pragma unroll
        for (int j = 0; j < 8; j++)
            #pragma unroll
            for (int r = 0; r < 4; r++) acc[i][j][r] = 0.f;

    stage(0, 0); cp_commit();

    int NT = K >> 5;
    for (int kt = 0; kt < NT; kt++) {
        if (kt + 1 < NT) {
            stage((kt + 1) & 1, kt + 1);
            cp_commit();
            cp_wait<1>();
        } else {
            cp_wait<0>();
        }
        __syncthreads();

        const float* Ab = As + (kt & 1)*TS;
        const float* Bb = Bs + (kt & 1)*TS;
        #pragma unroll
        for (int ks = 0; ks < 4; ks++) {
            int kb = ks * 8;
            uint32_t a[4][4], b[8][2];
            #pragma unroll
            for (int mt = 0; mt < 4; mt++) {
                int mr = wm0 + mt*16;
                a[mt][0] = __float_as_uint(Ab[(mr + g    )*ST + kb + tq    ]);
                a[mt][1] = __float_as_uint(Ab[(mr + g + 8)*ST + kb + tq    ]);
                a[mt][2] = __float_as_uint(Ab[(mr + g    )*ST + kb + tq + 4]);
                a[mt][3] = __float_as_uint(Ab[(mr + g + 8)*ST + kb + tq + 4]);
            }
            #pragma unroll
            for (int nt = 0; nt < 8; nt++) {
                int nr = wn0 + nt*8 + g;
                b[nt][0] = __float_as_uint(Bb[nr*ST + kb + tq    ]);
                b[nt][1] = __float_as_uint(Bb[nr*ST + kb + tq + 4]);
            }
            #pragma unroll
            for (int mt = 0; mt < 4; mt++)
                #pragma unroll
                for (int nt = 0; nt < 8; nt++)
                    mma_tf32(acc[mt][nt], a[mt], b[nt]);
        }
        __syncthreads();
    }

    // ---- epilogue (float2 stores) ----
    #pragma unroll
    for (int mt = 0; mt < 4; mt++) {
        int m0 = row0 + wm0 + mt*16 + g;
        #pragma unroll
        for (int nt = 0; nt < 8; nt++) {
            int n = col0 + wn0 + nt*8 + 2*tq;
            float bx = 0.f, by = 0.f;
            if (bias) { bx = bias[n]; by = bias[n+1]; }
            #pragma unroll
            for (int half = 0; half < 2; half++) {
                int m = m0 + half*8;
                float vx = acc[mt][nt][half*2+0] + bx;
                float vy = acc[mt][nt][half*2+1] + by;
                size_t ci = (size_t)m * ldc + n;
                if (resid) {
                    float2 rr = *reinterpret_cast<const float2*>(&resid[ci]);
                    vx += rr.x; vy += rr.y;
                }
                if (relu) { vx = fmaxf(vx, 0.f); vy = fmaxf(vy, 0.f); }
                if (round_out) { vx = to_tf32(vx); vy = to_tf32(vy); }
                *reinterpret_cast<float2*>(&C[ci]) = make_float2(vx, vy);
            }
        }
    }
}

// ------------------- launcher ---------------------------------------------------
extern "C" void kernel_launch(void* const* d_in, const int* in_sizes, int n_in,
                              void* d_out, int out_size) {
    const float* x   = (const float*)d_in[0];
    const float* Wq  = (const float*)d_in[1];
    const float* Wk  = (const float*)d_in[2];
    const float* Wv  = (const float*)d_in[3];
    const float* Wo  = (const float*)d_in[4];
    const float* bo  = (const float*)d_in[5];
    const float* W1  = (const float*)d_in[6];
    const float* b1  = (const float*)d_in[7];
    const float* W2  = (const float*)d_in[8];
    const float* b2  = (const float*)d_in[9];
    const float* g1  = (const float*)d_in[10];
    const float* be1 = (const float*)d_in[11];
    const float* g2  = (const float*)d_in[12];
    const float* be2 = (const float*)d_in[13];
    float* out = (float*)d_out;

    float *h, *qkv, *o, *h2, *ff, *wqkvT, *woT, *w1T, *w2T;
    cudaGetSymbolAddress((void**)&h,     g_h);
    cudaGetSymbolAddress((void**)&qkv,   g_qkv);
    cudaGetSymbolAddress((void**)&o,     g_o);
    cudaGetSymbolAddress((void**)&h2,    g_h2);
    cudaGetSymbolAddress((void**)&ff,    g_ff);
    cudaGetSymbolAddress((void**)&wqkvT, g_WqkvT);
    cudaGetSymbolAddress((void**)&woT,   g_WoT);
    cudaGetSymbolAddress((void**)&w1T,   g_W1T);
    cudaGetSymbolAddress((void**)&w2T,   g_W2T);

    const int FLASH_SMEM = (128*68 + 128*68 + 128*72) * 4;   // 106496
    const int GEMM_SMEM  = 4 * 128 * 36 * 4;                 // 73728
    static int smem_set = 0;
    if (!smem_set) {
        cudaFuncSetAttribute(flash_kernel,
                             cudaFuncAttributeMaxDynamicSharedMemorySize, FLASH_SMEM);
        cudaFuncSetAttribute(mma_gemm,
                             cudaFuncAttributeMaxDynamicSharedMemorySize, GEMM_SMEM);
        smem_set = 1;
    }

    // weight prep: transposed [N][K] tf32 copies
    qkv_transpose<<<dim3(S3_/32, C_/32), dim3(32,8)>>>(Wq, Wk, Wv, wqkvT);
    wt_transpose<<<dim3(C_/32,  C_/32),  dim3(32,8)>>>(Wo, woT, C_,  C_);
    wt_transpose<<<dim3(FF_/32, C_/32),  dim3(32,8)>>>(W1, w1T, C_,  FF_);
    wt_transpose<<<dim3(C_/32,  FF_/32), dim3(32,8)>>>(W2, w2T, FF_, C_);

    // LN1
    ln_kernel<<<BT_, 256>>>(x, g1, be1, h);

    // qkv = h @ Wqkv
    mma_gemm<<<dim3(S3_/128, BT_/128), 128, GEMM_SMEM>>>(
        h, C_, wqkvT, C_, qkv, S3_, nullptr, nullptr, 0, 1);

    // fused attention -> o
    flash_kernel<<<dim3(T_/128, B_*H_), 256, FLASH_SMEM>>>(qkv, o);

    // x1 = x + o @ Wo + bo -> d_out
    mma_gemm<<<dim3(C_/128, BT_/128), 128, GEMM_SMEM>>>(
        o, C_, woT, C_, out, C_, bo, x, 0, 0);

    // LN2
    ln_kernel<<<BT_, 256>>>(out, g2, be2, h2);

    // ff = relu(h2 @ W1 + b1)
    mma_gemm<<<dim3(FF_/128, BT_/128), 128, GEMM_SMEM>>>(
        h2, C_, w1T, C_, ff, FF_, b1, nullptr, 1, 1);

    // out = x1 + ff @ W2 + b2
    mma_gemm<<<dim3(C_/128, BT_/128), 128, GEMM_SMEM>>>(
        ff, FF_, w2T, FF_, out, C_, b2, out, 0, 0);
}